// round 3
// baseline (speedup 1.0000x reference)
#include <cuda_runtime.h>
#include <cuda_bf16.h>

// ---------------- problem constants ----------------
#define BT     96          // B*T
#define NTOK   1000        // N
#define M_TOT  96000       // B*T*N tokens
#define DIM    256         // D
#define EDIM   1024        // E = 4D
#define HN     8           // heads
#define HDIM   32          // head dim
#define RN     32          // low-rank R

// ---------------- scratch (device bss) ----------------
__device__ float g_x1[M_TOT * DIM];
__device__ float g_z1[M_TOT * DIM];
__device__ float g_G [M_TOT * EDIM];     // silu(h1)*h2
__device__ float g_ffn[M_TOT * DIM];
__device__ float g_L [M_TOT * DIM];      // attn logits, col = h*32+r
__device__ float g_xv[M_TOT * DIM];
__device__ float g_weff[DIM * DIM];
__device__ float g_abias[DIM];
__device__ float g_colmax[BT * DIM];
__device__ float g_colsum[BT * DIM];
__device__ float g_vmid[BT * HN * RN * HDIM];

// ---------------- helpers ----------------
__device__ __forceinline__ float sigm(float v) { return 1.f / (1.f + __expf(-v)); }

__device__ __forceinline__ float tf32r(float f) {
    unsigned u;
    asm("cvt.rna.tf32.f32 %0, %1;" : "=r"(u) : "f"(f));
    return __uint_as_float(u);
}

__device__ __forceinline__ void mma8(float* c, const unsigned* a, const unsigned* b) {
    asm volatile(
        "mma.sync.aligned.m16n8k8.row.col.f32.tf32.tf32.f32 "
        "{%0,%1,%2,%3},{%4,%5,%6,%7},{%8,%9},{%0,%1,%2,%3};"
        : "+f"(c[0]), "+f"(c[1]), "+f"(c[2]), "+f"(c[3])
        : "r"(a[0]), "r"(a[1]), "r"(a[2]), "r"(a[3]), "r"(b[0]), "r"(b[1]));
}

// ---------------- K0: Weff = (Wq . key^T)/sqrt(HD), abias from bq ----------------
__global__ void k_weff(const float* __restrict__ Wq, const float* __restrict__ bq,
                       const float* __restrict__ key) {
    const int i = blockIdx.x;       // input channel
    const int c = threadIdx.x;      // output col = h*32 + r
    const int h = c >> 5, r = c & 31;
    const float sc = 0.17677669529663687f;   // 1/sqrt(32)
    float s = 0.f;
#pragma unroll
    for (int d = 0; d < 32; d++)
        s += Wq[i * DIM + h * 32 + d] * key[(r * HN + h) * HDIM + d];
    g_weff[i * DIM + c] = s * sc;
    if (i == 0) {
        float b = 0.f;
#pragma unroll
        for (int d = 0; d < 32; d++)
            b += bq[h * 32 + d] * key[(r * HN + h) * HDIM + d];
        g_abias[c] = b * sc;
    }
}

// ---------------- K1: fused RMSNorms (one warp = one token) ----------------
__global__ __launch_bounds__(256) void k_norm(
    const float* __restrict__ x, const float* __restrict__ z,
    const float* __restrict__ w1, const float* __restrict__ w2,
    const float* __restrict__ ga, const float* __restrict__ de)
{
    const int warp = threadIdx.x >> 5, lane = threadIdx.x & 31;
    const long tok = (long)blockIdx.x * 8 + warp;
    const float sg = sigm(ga[0]), sd = sigm(de[0]);

    const float4* xr = (const float4*)x + tok * 64;
    const float4* zr = (const float4*)z + tok * 64;
    float4 xa = xr[lane], xb = xr[lane + 32];

    float ss = xa.x*xa.x + xa.y*xa.y + xa.z*xa.z + xa.w*xa.w
             + xb.x*xb.x + xb.y*xb.y + xb.z*xb.z + xb.w*xb.w;
#pragma unroll
    for (int o = 16; o; o >>= 1) ss += __shfl_xor_sync(0xffffffffu, ss, o);
    const float r1 = rsqrtf(ss * (1.f / 256.f) + 1e-6f);

    float4 wa = ((const float4*)w1)[lane], wb = ((const float4*)w1)[lane + 32];
    float4 x1a, x1b;
    x1a.x = xa.x*r1*wa.x; x1a.y = xa.y*r1*wa.y; x1a.z = xa.z*r1*wa.z; x1a.w = xa.w*r1*wa.w;
    x1b.x = xb.x*r1*wb.x; x1b.y = xb.y*r1*wb.y; x1b.z = xb.z*r1*wb.z; x1b.w = xb.w*r1*wb.w;
    float4* x1o = (float4*)g_x1 + tok * 64;
    x1o[lane] = x1a; x1o[lane + 32] = x1b;

    float4 za = zr[lane], zb = zr[lane + 32];
    float4 ya, yb;
    ya.x = sg*x1a.x + sd*za.x; ya.y = sg*x1a.y + sd*za.y;
    ya.z = sg*x1a.z + sd*za.z; ya.w = sg*x1a.w + sd*za.w;
    yb.x = sg*x1b.x + sd*zb.x; yb.y = sg*x1b.y + sd*zb.y;
    yb.z = sg*x1b.z + sd*zb.z; yb.w = sg*x1b.w + sd*zb.w;

    float s2 = ya.x*ya.x + ya.y*ya.y + ya.z*ya.z + ya.w*ya.w
             + yb.x*yb.x + yb.y*yb.y + yb.z*yb.z + yb.w*yb.w;
#pragma unroll
    for (int o = 16; o; o >>= 1) s2 += __shfl_xor_sync(0xffffffffu, s2, o);
    const float r2 = rsqrtf(s2 * (1.f / 256.f) + 1e-6f);

    float4 va = ((const float4*)w2)[lane], vb = ((const float4*)w2)[lane + 32];
    float4 z1a, z1b;
    z1a.x = ya.x*r2*va.x; z1a.y = ya.y*r2*va.y; z1a.z = ya.z*r2*va.z; z1a.w = ya.w*r2*va.w;
    z1b.x = yb.x*r2*vb.x; z1b.y = yb.y*r2*vb.y; z1b.z = yb.z*r2*vb.z; z1b.w = yb.w*r2*vb.w;
    float4* z1o = (float4*)g_z1 + tok * 64;
    z1o[lane] = z1a; z1o[lane + 32] = z1b;
}

// ---------------- K2: dual SwiGLU GEMM: G = silu(x1@W1+b1)*(x1@W2+b2) ----------------
// block tile 128x64, 8 warps (2x4), warp tile 64x16; K step 32.
__global__ __launch_bounds__(256) void k_dualffn(
    const float* __restrict__ W1, const float* __restrict__ b1,
    const float* __restrict__ W2, const float* __restrict__ b2)
{
    __shared__ float As[128][36];
    __shared__ float B1s[32][72];
    __shared__ float B2s[32][72];
    const int K = DIM, N = EDIM;
    const int tid = threadIdx.x;
    const int warp = tid >> 5, lane = tid & 31, grp = lane >> 2, tg = lane & 3;
    const int wm0 = (warp >> 2) * 64, wn0 = (warp & 3) * 16;
    const int m0 = blockIdx.y * 128, n0 = blockIdx.x * 64;

    float acc1[4][2][4], acc2[4][2][4];
#pragma unroll
    for (int a = 0; a < 4; a++)
#pragma unroll
        for (int b = 0; b < 2; b++)
#pragma unroll
            for (int c = 0; c < 4; c++) { acc1[a][b][c] = 0.f; acc2[a][b][c] = 0.f; }

    int arow[4], akq[4], brw[2], bnq[2];
#pragma unroll
    for (int i = 0; i < 4; i++) { int e = tid + i * 256; arow[i] = e >> 3; akq[i] = e & 7; }
#pragma unroll
    for (int i = 0; i < 2; i++) { int e = tid + i * 256; brw[i] = e >> 4; bnq[i] = e & 15; }

    float4 ar[4], b1r[2], b2r[2];
    const int KT = K >> 5;

#define LOADG_D(kt) do { int kb = (kt) * 32;                                              \
    _Pragma("unroll") for (int i = 0; i < 4; i++)                                         \
        ar[i] = *(const float4*)(g_x1 + (long)(m0 + arow[i]) * K + kb + akq[i] * 4);      \
    _Pragma("unroll") for (int i = 0; i < 2; i++) {                                       \
        b1r[i] = *(const float4*)(W1 + (long)(kb + brw[i]) * N + n0 + bnq[i] * 4);        \
        b2r[i] = *(const float4*)(W2 + (long)(kb + brw[i]) * N + n0 + bnq[i] * 4); } } while (0)

#define STOS_D() do {                                                                     \
    _Pragma("unroll") for (int i = 0; i < 4; i++) { float4 v = ar[i];                     \
        v.x = tf32r(v.x); v.y = tf32r(v.y); v.z = tf32r(v.z); v.w = tf32r(v.w);           \
        *(float4*)&As[arow[i]][akq[i] * 4] = v; }                                         \
    _Pragma("unroll") for (int i = 0; i < 2; i++) { float4 u = b1r[i], w = b2r[i];        \
        u.x = tf32r(u.x); u.y = tf32r(u.y); u.z = tf32r(u.z); u.w = tf32r(u.w);           \
        w.x = tf32r(w.x); w.y = tf32r(w.y); w.z = tf32r(w.z); w.w = tf32r(w.w);           \
        *(float4*)&B1s[brw[i]][bnq[i] * 4] = u;                                           \
        *(float4*)&B2s[brw[i]][bnq[i] * 4] = w; } } while (0)

    LOADG_D(0); STOS_D();
    for (int kt = 0; kt < KT; kt++) {
        __syncthreads();
        if (kt + 1 < KT) LOADG_D(kt + 1);
#pragma unroll
        for (int kk = 0; kk < 4; kk++) {
            const int ks = kk * 8;
            unsigned a[4][4], bb1[2][2], bb2[2][2];
#pragma unroll
            for (int mf = 0; mf < 4; mf++) {
                int m = wm0 + mf * 16 + grp;
                a[mf][0] = __float_as_uint(As[m][ks + tg]);
                a[mf][1] = __float_as_uint(As[m + 8][ks + tg]);
                a[mf][2] = __float_as_uint(As[m][ks + tg + 4]);
                a[mf][3] = __float_as_uint(As[m + 8][ks + tg + 4]);
            }
#pragma unroll
            for (int nf = 0; nf < 2; nf++) {
                int n = wn0 + nf * 8 + grp;
                bb1[nf][0] = __float_as_uint(B1s[ks + tg][n]);
                bb1[nf][1] = __float_as_uint(B1s[ks + tg + 4][n]);
                bb2[nf][0] = __float_as_uint(B2s[ks + tg][n]);
                bb2[nf][1] = __float_as_uint(B2s[ks + tg + 4][n]);
            }
#pragma unroll
            for (int mf = 0; mf < 4; mf++)
#pragma unroll
                for (int nf = 0; nf < 2; nf++) {
                    mma8(acc1[mf][nf], a[mf], bb1[nf]);
                    mma8(acc2[mf][nf], a[mf], bb2[nf]);
                }
        }
        __syncthreads();
        if (kt + 1 < KT) STOS_D();
    }
#undef LOADG_D
#undef STOS_D

#pragma unroll
    for (int mf = 0; mf < 4; mf++) {
        const int gm = m0 + wm0 + mf * 16 + grp;
#pragma unroll
        for (int nf = 0; nf < 2; nf++) {
            const int gn = n0 + wn0 + nf * 8 + tg * 2;
            const float c1x = b1[gn], c1y = b1[gn + 1];
            const float c2x = b2[gn], c2y = b2[gn + 1];
            float h1, h2;
            float2 o0, o1;
            h1 = acc1[mf][nf][0] + c1x; h2 = acc2[mf][nf][0] + c2x; o0.x = h1 * sigm(h1) * h2;
            h1 = acc1[mf][nf][1] + c1y; h2 = acc2[mf][nf][1] + c2y; o0.y = h1 * sigm(h1) * h2;
            h1 = acc1[mf][nf][2] + c1x; h2 = acc2[mf][nf][2] + c2x; o1.x = h1 * sigm(h1) * h2;
            h1 = acc1[mf][nf][3] + c1y; h2 = acc2[mf][nf][3] + c2y; o1.y = h1 * sigm(h1) * h2;
            *(float2*)(g_G + (long)gm * EDIM + gn) = o0;
            *(float2*)(g_G + (long)(gm + 8) * EDIM + gn) = o1;
        }
    }
}

// ---------------- K3: generic GEMM C = A@W + bias, 128x128 tile ----------------
// mode 0: A=g_G,  C=g_ffn, bias=ext (b3)
// mode 1: A=g_z1, C=g_L,   bias=g_abias
// mode 2: A=g_x1, C=g_xv,  bias=ext (bv)
__global__ __launch_bounds__(256) void k_gemm(
    int mode, const float* __restrict__ W, const float* __restrict__ biasExt,
    int K, int N)
{
    const float* __restrict__ A = (mode == 0) ? g_G : (mode == 1) ? g_z1 : g_x1;
    float* __restrict__ C = (mode == 0) ? g_ffn : (mode == 1) ? g_L : g_xv;
    const float* __restrict__ bias = (mode == 1) ? g_abias : biasExt;

    __shared__ float As[128][36];
    __shared__ float Bs[32][136];
    const int tid = threadIdx.x;
    const int warp = tid >> 5, lane = tid & 31, grp = lane >> 2, tg = lane & 3;
    const int wm0 = (warp >> 2) * 64, wn0 = (warp & 3) * 32;
    const int m0 = blockIdx.y * 128, n0 = blockIdx.x * 128;

    float acc[4][4][4];
#pragma unroll
    for (int a = 0; a < 4; a++)
#pragma unroll
        for (int b = 0; b < 4; b++)
#pragma unroll
            for (int c = 0; c < 4; c++) acc[a][b][c] = 0.f;

    int arow[4], akq[4], brw[4], bnq[4];
#pragma unroll
    for (int i = 0; i < 4; i++) {
        int e = tid + i * 256;
        arow[i] = e >> 3; akq[i] = e & 7;
        brw[i] = e >> 5;  bnq[i] = e & 31;
    }

    float4 ar[4], br[4];
    const int KT = K >> 5;

#define LOADG_G(kt) do { int kb = (kt) * 32;                                              \
    _Pragma("unroll") for (int i = 0; i < 4; i++)                                         \
        ar[i] = *(const float4*)(A + (long)(m0 + arow[i]) * K + kb + akq[i] * 4);         \
    _Pragma("unroll") for (int i = 0; i < 4; i++)                                         \
        br[i] = *(const float4*)(W + (long)(kb + brw[i]) * N + n0 + bnq[i] * 4); } while (0)

#define STOS_G() do {                                                                     \
    _Pragma("unroll") for (int i = 0; i < 4; i++) { float4 v = ar[i];                     \
        v.x = tf32r(v.x); v.y = tf32r(v.y); v.z = tf32r(v.z); v.w = tf32r(v.w);           \
        *(float4*)&As[arow[i]][akq[i] * 4] = v;                                           \
        float4 u = br[i];                                                                 \
        u.x = tf32r(u.x); u.y = tf32r(u.y); u.z = tf32r(u.z); u.w = tf32r(u.w);           \
        *(float4*)&Bs[brw[i]][bnq[i] * 4] = u; } } while (0)

    LOADG_G(0); STOS_G();
    for (int kt = 0; kt < KT; kt++) {
        __syncthreads();
        if (kt + 1 < KT) LOADG_G(kt + 1);
#pragma unroll
        for (int kk = 0; kk < 4; kk++) {
            const int ks = kk * 8;
            unsigned a[4][4], b[4][2];
#pragma unroll
            for (int mf = 0; mf < 4; mf++) {
                int m = wm0 + mf * 16 + grp;
                a[mf][0] = __float_as_uint(As[m][ks + tg]);
                a[mf][1] = __float_as_uint(As[m + 8][ks + tg]);
                a[mf][2] = __float_as_uint(As[m][ks + tg + 4]);
                a[mf][3] = __float_as_uint(As[m + 8][ks + tg + 4]);
            }
#pragma unroll
            for (int nf = 0; nf < 4; nf++) {
                int n = wn0 + nf * 8 + grp;
                b[nf][0] = __float_as_uint(Bs[ks + tg][n]);
                b[nf][1] = __float_as_uint(Bs[ks + tg + 4][n]);
            }
#pragma unroll
            for (int mf = 0; mf < 4; mf++)
#pragma unroll
                for (int nf = 0; nf < 4; nf++)
                    mma8(acc[mf][nf], a[mf], b[nf]);
        }
        __syncthreads();
        if (kt + 1 < KT) STOS_G();
    }
#undef LOADG_G
#undef STOS_G

#pragma unroll
    for (int mf = 0; mf < 4; mf++) {
        const int gm = m0 + wm0 + mf * 16 + grp;
#pragma unroll
        for (int nf = 0; nf < 4; nf++) {
            const int gn = n0 + wn0 + nf * 8 + tg * 2;
            const float2 bb = *(const float2*)(bias + gn);
            float2 o0 = { acc[mf][nf][0] + bb.x, acc[mf][nf][1] + bb.y };
            float2 o1 = { acc[mf][nf][2] + bb.x, acc[mf][nf][3] + bb.y };
            *(float2*)(C + (long)gm * N + gn) = o0;
            *(float2*)(C + (long)(gm + 8) * N + gn) = o1;
        }
    }
}

// ---------------- K4: per-(bt,col) online max/sum over n (axis-2 softmax stats) ----------------
__global__ __launch_bounds__(256) void k_colstats() {
    const int bt = blockIdx.x, c = threadIdx.x;
    const float* base = g_L + (long)bt * NTOK * DIM + c;
    float m = -3.0e38f, s = 0.f;
    for (int n0 = 0; n0 < NTOK; n0 += 8) {
        float v[8];
#pragma unroll
        for (int j = 0; j < 8; j++) v[j] = base[(long)(n0 + j) * DIM];
        float lm = v[0];
#pragma unroll
        for (int j = 1; j < 8; j++) lm = fmaxf(lm, v[j]);
        const float nm = fmaxf(m, lm);
        s *= __expf(m - nm);
#pragma unroll
        for (int j = 0; j < 8; j++) s += __expf(v[j] - nm);
        m = nm;
    }
    g_colmax[bt * DIM + c] = m;
    g_colsum[bt * DIM + c] = s;
}

// ---------------- K5: v_mid[bt,h] = S1^T @ xv  (S1 = row softmax over r) ----------------
__global__ __launch_bounds__(256) void k_attmid() {
    const int bt = blockIdx.x, h = blockIdx.y;
    __shared__ float Ls[32][32];
    __shared__ float XVs[32][32];
    __shared__ float S1s[32][32];
    const int tid = threadIdx.x, warp = tid >> 5, lane = tid & 31;
    float acc[4] = {0.f, 0.f, 0.f, 0.f};

    for (int ch = 0; ch < 32; ch++) {
        const int nb = ch * 32;
#pragma unroll
        for (int i = 0; i < 4; i++) {
            const int e = tid + i * 256;
            const int n = e >> 5, c = e & 31;
            const int ng = nb + n;
            const bool valid = ng < NTOK;
            const long row = (long)(bt * NTOK + ng) * DIM + h * 32;
            Ls[n][c]  = valid ? g_L[row + c]  : 0.f;
            XVs[n][c] = valid ? g_xv[row + c] : 0.f;
        }
        __syncthreads();
#pragma unroll
        for (int j = 0; j < 4; j++) {
            const int n = warp * 4 + j;
            const float v = Ls[n][lane];
            float mx = v;
#pragma unroll
            for (int o = 16; o; o >>= 1) mx = fmaxf(mx, __shfl_xor_sync(0xffffffffu, mx, o));
            const float e0 = __expf(v - mx);
            float sm = e0;
#pragma unroll
            for (int o = 16; o; o >>= 1) sm += __shfl_xor_sync(0xffffffffu, sm, o);
            float s1 = e0 / sm;
            if (nb + n >= NTOK) s1 = 0.f;
            S1s[n][lane] = s1;
        }
        __syncthreads();
#pragma unroll 8
        for (int n = 0; n < 32; n++) {
            const float xvv = XVs[n][lane];
#pragma unroll
            for (int j = 0; j < 4; j++) acc[j] += S1s[n][warp * 4 + j] * xvv;
        }
        __syncthreads();
    }
#pragma unroll
    for (int j = 0; j < 4; j++)
        g_vmid[(((long)bt * HN + h) * RN + warp * 4 + j) * HDIM + lane] = acc[j];
}

// ---------------- K6: S2 softmax + v_out + final combine ----------------
__global__ __launch_bounds__(256) void k_final(
    float* __restrict__ out,
    const float* __restrict__ al, const float* __restrict__ be,
    const float* __restrict__ ma, const float* __restrict__ mb)
{
    __shared__ float vm[HN * RN * HDIM];   // 8192 floats = 32KB
    __shared__ float s2s[256];
    const int bt = blockIdx.x / 50;
    const int ch = blockIdx.x % 50;
    const int tid = threadIdx.x;
    const int h = tid >> 5, d = tid & 31;
    const float sa = sigm(al[0]), sb = sigm(be[0]);
    const float sva = sigm(ma[h]), svb = sigm(mb[h]);

#pragma unroll
    for (int i = 0; i < 32; i++)
        vm[tid + i * 256] = g_vmid[(long)bt * 8192 + tid + i * 256];

    const float cm = g_colmax[bt * DIM + tid];
    const float ci = 1.f / g_colsum[bt * DIM + tid];
    __syncthreads();

    for (int t = 0; t < 20; t++) {
        const long tok = (long)bt * NTOK + ch * 20 + t;
        const long ro = tok * DIM + tid;
        const float l = g_L[ro];
        s2s[tid] = __expf(l - cm) * ci;
        __syncthreads();
        float acc = 0.f;
#pragma unroll
        for (int r = 0; r < 32; r++)
            acc += s2s[h * 32 + r] * vm[(h * 32 + r) * 32 + d];
        const float xvv = g_xv[ro];
        out[ro] = sa * g_ffn[ro] + sb * (sva * xvv + svb * acc);
        __syncthreads();
    }
}

// ---------------- launch ----------------
extern "C" void kernel_launch(void* const* d_in, const int* in_sizes, int n_in,
                              void* d_out, int out_size) {
    (void)in_sizes; (void)n_in; (void)out_size;
    const float* x     = (const float*)d_in[0];
    const float* z     = (const float*)d_in[1];
    const float* n1w   = (const float*)d_in[2];
    const float* n2w   = (const float*)d_in[3];
    const float* alpha = (const float*)d_in[4];
    const float* beta  = (const float*)d_in[5];
    const float* gamma = (const float*)d_in[6];
    const float* delta = (const float*)d_in[7];
    const float* Wq    = (const float*)d_in[8];
    const float* bq    = (const float*)d_in[9];
    const float* key   = (const float*)d_in[10];
    const float* Wv    = (const float*)d_in[11];
    const float* bv    = (const float*)d_in[12];
    const float* mha_a = (const float*)d_in[13];
    const float* mha_b = (const float*)d_in[14];
    const float* W1    = (const float*)d_in[15];
    const float* b1    = (const float*)d_in[16];
    const float* W2    = (const float*)d_in[17];
    const float* b2    = (const float*)d_in[18];
    const float* W3    = (const float*)d_in[19];
    const float* b3    = (const float*)d_in[20];
    float* out = (float*)d_out;

    k_weff<<<256, 256>>>(Wq, bq, key);
    k_norm<<<M_TOT / 8, 256>>>(x, z, n1w, n2w, gamma, delta);
    k_dualffn<<<dim3(EDIM / 64, M_TOT / 128), 256>>>(W1, b1, W2, b2);
    k_gemm<<<dim3(DIM / 128, M_TOT / 128), 256>>>(0, W3, b3, EDIM, DIM);   // ffn
    k_gemm<<<dim3(DIM / 128, M_TOT / 128), 256>>>(1, g_weff, nullptr, DIM, DIM); // L (bias internal; W arg resolved on device side)
    k_gemm<<<dim3(DIM / 128, M_TOT / 128), 256>>>(2, Wv, bv, DIM, DIM);    // xv
    k_colstats<<<BT, 256>>>();
    k_attmid<<<dim3(BT, HN), 256>>>();
    k_final<<<BT * 50, 256>>>(out, alpha, beta, mha_a, mha_b);
}

// round 6
// speedup vs baseline: 1.1982x; 1.1982x over previous
#include <cuda_runtime.h>
#include <cuda_bf16.h>

// ---------------- problem constants ----------------
#define BT     96          // B*T
#define NTOK   1000        // N
#define M_TOT  96000       // B*T*N tokens
#define DIM    256         // D
#define EDIM   1024        // E = 4D
#define HN     8           // heads
#define HDIM   32          // head dim
#define RN     32          // low-rank R

// ---------------- scratch (device bss) ----------------
__device__ float g_x1[M_TOT * DIM];
__device__ float g_z1[M_TOT * DIM];
__device__ float g_G [M_TOT * EDIM];     // silu(h1)*h2
__device__ float g_ffn[M_TOT * DIM];
__device__ float g_L [M_TOT * DIM];      // attn logits, col = h*32+r
__device__ float g_xv[M_TOT * DIM];
__device__ float g_weff[DIM * DIM];
__device__ float g_abias[DIM];
__device__ float g_colmax[BT * DIM];
__device__ float g_colsum[BT * DIM];
__device__ float g_cmax_p[8 * BT * DIM];
__device__ float g_csum_p[8 * BT * DIM];
__device__ float g_vmid[BT * HN * RN * HDIM];

// ---------------- helpers ----------------
__device__ __forceinline__ float sigm(float v) { return 1.f / (1.f + __expf(-v)); }

__device__ __forceinline__ float tf32r(float f) {
    unsigned u;
    asm("cvt.rna.tf32.f32 %0, %1;" : "=r"(u) : "f"(f));
    return __uint_as_float(u);
}

__device__ __forceinline__ void mma8(float* c, const unsigned* a, const unsigned* b) {
    asm volatile(
        "mma.sync.aligned.m16n8k8.row.col.f32.tf32.tf32.f32 "
        "{%0,%1,%2,%3},{%4,%5,%6,%7},{%8,%9},{%0,%1,%2,%3};"
        : "+f"(c[0]), "+f"(c[1]), "+f"(c[2]), "+f"(c[3])
        : "r"(a[0]), "r"(a[1]), "r"(a[2]), "r"(a[3]), "r"(b[0]), "r"(b[1]));
}

// ---------------- K0: Weff = (Wq . key^T)/sqrt(HD), abias from bq ----------------
__global__ void k_weff(const float* __restrict__ Wq, const float* __restrict__ bq,
                       const float* __restrict__ key) {
    const int i = blockIdx.x;       // input channel
    const int c = threadIdx.x;      // output col = h*32 + r
    const int h = c >> 5, r = c & 31;
    const float sc = 0.17677669529663687f;   // 1/sqrt(32)
    float s = 0.f;
#pragma unroll
    for (int d = 0; d < 32; d++)
        s += Wq[i * DIM + h * 32 + d] * key[(r * HN + h) * HDIM + d];
    g_weff[i * DIM + c] = s * sc;
    if (i == 0) {
        float b = 0.f;
#pragma unroll
        for (int d = 0; d < 32; d++)
            b += bq[h * 32 + d] * key[(r * HN + h) * HDIM + d];
        g_abias[c] = b * sc;
    }
}

// ---------------- K1: fused RMSNorms (one warp = one token) ----------------
__global__ __launch_bounds__(256) void k_norm(
    const float* __restrict__ x, const float* __restrict__ z,
    const float* __restrict__ w1, const float* __restrict__ w2,
    const float* __restrict__ ga, const float* __restrict__ de)
{
    const int warp = threadIdx.x >> 5, lane = threadIdx.x & 31;
    const long tok = (long)blockIdx.x * 8 + warp;
    const float sg = sigm(ga[0]), sd = sigm(de[0]);

    const float4* xr = (const float4*)x + tok * 64;
    const float4* zr = (const float4*)z + tok * 64;
    float4 xa = xr[lane], xb = xr[lane + 32];

    float ss = xa.x*xa.x + xa.y*xa.y + xa.z*xa.z + xa.w*xa.w
             + xb.x*xb.x + xb.y*xb.y + xb.z*xb.z + xb.w*xb.w;
#pragma unroll
    for (int o = 16; o; o >>= 1) ss += __shfl_xor_sync(0xffffffffu, ss, o);
    const float r1 = rsqrtf(ss * (1.f / 256.f) + 1e-6f);

    float4 wa = ((const float4*)w1)[lane], wb = ((const float4*)w1)[lane + 32];
    float4 x1a, x1b;
    x1a.x = xa.x*r1*wa.x; x1a.y = xa.y*r1*wa.y; x1a.z = xa.z*r1*wa.z; x1a.w = xa.w*r1*wa.w;
    x1b.x = xb.x*r1*wb.x; x1b.y = xb.y*r1*wb.y; x1b.z = xb.z*r1*wb.z; x1b.w = xb.w*r1*wb.w;
    float4* x1o = (float4*)g_x1 + tok * 64;
    x1o[lane] = x1a; x1o[lane + 32] = x1b;

    float4 za = zr[lane], zb = zr[lane + 32];
    float4 ya, yb;
    ya.x = sg*x1a.x + sd*za.x; ya.y = sg*x1a.y + sd*za.y;
    ya.z = sg*x1a.z + sd*za.z; ya.w = sg*x1a.w + sd*za.w;
    yb.x = sg*x1b.x + sd*zb.x; yb.y = sg*x1b.y + sd*zb.y;
    yb.z = sg*x1b.z + sd*zb.z; yb.w = sg*x1b.w + sd*zb.w;

    float s2 = ya.x*ya.x + ya.y*ya.y + ya.z*ya.z + ya.w*ya.w
             + yb.x*yb.x + yb.y*yb.y + yb.z*yb.z + yb.w*yb.w;
#pragma unroll
    for (int o = 16; o; o >>= 1) s2 += __shfl_xor_sync(0xffffffffu, s2, o);
    const float r2 = rsqrtf(s2 * (1.f / 256.f) + 1e-6f);

    float4 va = ((const float4*)w2)[lane], vb = ((const float4*)w2)[lane + 32];
    float4 z1a, z1b;
    z1a.x = ya.x*r2*va.x; z1a.y = ya.y*r2*va.y; z1a.z = ya.z*r2*va.z; z1a.w = ya.w*r2*va.w;
    z1b.x = yb.x*r2*vb.x; z1b.y = yb.y*r2*vb.y; z1b.z = yb.z*r2*vb.z; z1b.w = yb.w*r2*vb.w;
    float4* z1o = (float4*)g_z1 + tok * 64;
    z1o[lane] = z1a; z1o[lane + 32] = z1b;
}

// ---------------- K2: dual SwiGLU GEMM: G = silu(x1@W1+b1)*(x1@W2+b2) ----------------
// block tile 128x64, 8 warps (2x4), warp tile 64x16; K step 32.
__global__ __launch_bounds__(256, 2) void k_dualffn(
    const float* __restrict__ W1, const float* __restrict__ b1,
    const float* __restrict__ W2, const float* __restrict__ b2)
{
    __shared__ float As[128][36];
    __shared__ float B1s[32][72];
    __shared__ float B2s[32][72];
    const int K = DIM, N = EDIM;
    const int tid = threadIdx.x;
    const int warp = tid >> 5, lane = tid & 31, grp = lane >> 2, tg = lane & 3;
    const int wm0 = (warp >> 2) * 64, wn0 = (warp & 3) * 16;
    const int m0 = blockIdx.y * 128, n0 = blockIdx.x * 64;

    float acc1[4][2][4], acc2[4][2][4];
#pragma unroll
    for (int a = 0; a < 4; a++)
#pragma unroll
        for (int b = 0; b < 2; b++)
#pragma unroll
            for (int c = 0; c < 4; c++) { acc1[a][b][c] = 0.f; acc2[a][b][c] = 0.f; }

    int arow[4], akq[4], brw[2], bnq[2];
#pragma unroll
    for (int i = 0; i < 4; i++) { int e = tid + i * 256; arow[i] = e >> 3; akq[i] = e & 7; }
#pragma unroll
    for (int i = 0; i < 2; i++) { int e = tid + i * 256; brw[i] = e >> 4; bnq[i] = e & 15; }

    float4 ar[4], b1r[2], b2r[2];
    const int KT = K >> 5;

#define LOADG_D(kt) do { int kb = (kt) * 32;                                              \
    _Pragma("unroll") for (int i = 0; i < 4; i++)                                         \
        ar[i] = *(const float4*)(g_x1 + (long)(m0 + arow[i]) * K + kb + akq[i] * 4);      \
    _Pragma("unroll") for (int i = 0; i < 2; i++) {                                       \
        b1r[i] = *(const float4*)(W1 + (long)(kb + brw[i]) * N + n0 + bnq[i] * 4);        \
        b2r[i] = *(const float4*)(W2 + (long)(kb + brw[i]) * N + n0 + bnq[i] * 4); } } while (0)

#define STOS_D() do {                                                                     \
    _Pragma("unroll") for (int i = 0; i < 4; i++) { float4 v = ar[i];                     \
        v.x = tf32r(v.x); v.y = tf32r(v.y); v.z = tf32r(v.z); v.w = tf32r(v.w);           \
        *(float4*)&As[arow[i]][akq[i] * 4] = v; }                                         \
    _Pragma("unroll") for (int i = 0; i < 2; i++) { float4 u = b1r[i], w = b2r[i];        \
        u.x = tf32r(u.x); u.y = tf32r(u.y); u.z = tf32r(u.z); u.w = tf32r(u.w);           \
        w.x = tf32r(w.x); w.y = tf32r(w.y); w.z = tf32r(w.z); w.w = tf32r(w.w);           \
        *(float4*)&B1s[brw[i]][bnq[i] * 4] = u;                                           \
        *(float4*)&B2s[brw[i]][bnq[i] * 4] = w; } } while (0)

    LOADG_D(0); STOS_D();
    for (int kt = 0; kt < KT; kt++) {
        __syncthreads();
        if (kt + 1 < KT) LOADG_D(kt + 1);
#pragma unroll
        for (int kk = 0; kk < 4; kk++) {
            const int ks = kk * 8;
            unsigned a[4][4], bb1[2][2], bb2[2][2];
#pragma unroll
            for (int mf = 0; mf < 4; mf++) {
                int m = wm0 + mf * 16 + grp;
                a[mf][0] = __float_as_uint(As[m][ks + tg]);
                a[mf][1] = __float_as_uint(As[m + 8][ks + tg]);
                a[mf][2] = __float_as_uint(As[m][ks + tg + 4]);
                a[mf][3] = __float_as_uint(As[m + 8][ks + tg + 4]);
            }
#pragma unroll
            for (int nf = 0; nf < 2; nf++) {
                int n = wn0 + nf * 8 + grp;
                bb1[nf][0] = __float_as_uint(B1s[ks + tg][n]);
                bb1[nf][1] = __float_as_uint(B1s[ks + tg + 4][n]);
                bb2[nf][0] = __float_as_uint(B2s[ks + tg][n]);
                bb2[nf][1] = __float_as_uint(B2s[ks + tg + 4][n]);
            }
#pragma unroll
            for (int mf = 0; mf < 4; mf++)
#pragma unroll
                for (int nf = 0; nf < 2; nf++) {
                    mma8(acc1[mf][nf], a[mf], bb1[nf]);
                    mma8(acc2[mf][nf], a[mf], bb2[nf]);
                }
        }
        __syncthreads();
        if (kt + 1 < KT) STOS_D();
    }
#undef LOADG_D
#undef STOS_D

#pragma unroll
    for (int mf = 0; mf < 4; mf++) {
        const int gm = m0 + wm0 + mf * 16 + grp;
#pragma unroll
        for (int nf = 0; nf < 2; nf++) {
            const int gn = n0 + wn0 + nf * 8 + tg * 2;
            const float c1x = b1[gn], c1y = b1[gn + 1];
            const float c2x = b2[gn], c2y = b2[gn + 1];
            float h1, h2;
            float2 o0, o1;
            h1 = acc1[mf][nf][0] + c1x; h2 = acc2[mf][nf][0] + c2x; o0.x = h1 * sigm(h1) * h2;
            h1 = acc1[mf][nf][1] + c1y; h2 = acc2[mf][nf][1] + c2y; o0.y = h1 * sigm(h1) * h2;
            h1 = acc1[mf][nf][2] + c1x; h2 = acc2[mf][nf][2] + c2x; o1.x = h1 * sigm(h1) * h2;
            h1 = acc1[mf][nf][3] + c1y; h2 = acc2[mf][nf][3] + c2y; o1.y = h1 * sigm(h1) * h2;
            *(float2*)(g_G + (long)gm * EDIM + gn) = o0;
            *(float2*)(g_G + (long)(gm + 8) * EDIM + gn) = o1;
        }
    }
}

// ---------------- K3: generic GEMM C = A@W + bias, 128x128 tile ----------------
// mode 0: A=g_G,  C=g_ffn, bias=ext (b3)
// mode 1: A=g_z1, C=g_L,   bias=g_abias
// mode 2: A=g_x1, C=g_xv,  bias=ext (bv)
__global__ __launch_bounds__(256, 2) void k_gemm(
    int mode, const float* __restrict__ W, const float* __restrict__ biasExt,
    int K, int N)
{
    const float* __restrict__ A = (mode == 0) ? g_G : (mode == 1) ? g_z1 : g_x1;
    float* __restrict__ C = (mode == 0) ? g_ffn : (mode == 1) ? g_L : g_xv;
    const float* __restrict__ bias = (mode == 1) ? g_abias : biasExt;

    __shared__ float As[128][36];
    __shared__ float Bs[32][136];
    const int tid = threadIdx.x;
    const int warp = tid >> 5, lane = tid & 31, grp = lane >> 2, tg = lane & 3;
    const int wm0 = (warp >> 2) * 64, wn0 = (warp & 3) * 32;
    const int m0 = blockIdx.y * 128, n0 = blockIdx.x * 128;

    float acc[4][4][4];
#pragma unroll
    for (int a = 0; a < 4; a++)
#pragma unroll
        for (int b = 0; b < 4; b++)
#pragma unroll
            for (int c = 0; c < 4; c++) acc[a][b][c] = 0.f;

    int arow[4], akq[4], brw[4], bnq[4];
#pragma unroll
    for (int i = 0; i < 4; i++) {
        int e = tid + i * 256;
        arow[i] = e >> 3; akq[i] = e & 7;
        brw[i] = e >> 5;  bnq[i] = e & 31;
    }

    float4 ar[4], br[4];
    const int KT = K >> 5;

#define LOADG_G(kt) do { int kb = (kt) * 32;                                              \
    _Pragma("unroll") for (int i = 0; i < 4; i++)                                         \
        ar[i] = *(const float4*)(A + (long)(m0 + arow[i]) * K + kb + akq[i] * 4);         \
    _Pragma("unroll") for (int i = 0; i < 4; i++)                                         \
        br[i] = *(const float4*)(W + (long)(kb + brw[i]) * N + n0 + bnq[i] * 4); } while (0)

#define STOS_G() do {                                                                     \
    _Pragma("unroll") for (int i = 0; i < 4; i++) { float4 v = ar[i];                     \
        v.x = tf32r(v.x); v.y = tf32r(v.y); v.z = tf32r(v.z); v.w = tf32r(v.w);           \
        *(float4*)&As[arow[i]][akq[i] * 4] = v;                                           \
        float4 u = br[i];                                                                 \
        u.x = tf32r(u.x); u.y = tf32r(u.y); u.z = tf32r(u.z); u.w = tf32r(u.w);           \
        *(float4*)&Bs[brw[i]][bnq[i] * 4] = u; } } while (0)

    LOADG_G(0); STOS_G();
    for (int kt = 0; kt < KT; kt++) {
        __syncthreads();
        if (kt + 1 < KT) LOADG_G(kt + 1);
#pragma unroll
        for (int kk = 0; kk < 4; kk++) {
            const int ks = kk * 8;
            unsigned a[4][4], b[4][2];
#pragma unroll
            for (int mf = 0; mf < 4; mf++) {
                int m = wm0 + mf * 16 + grp;
                a[mf][0] = __float_as_uint(As[m][ks + tg]);
                a[mf][1] = __float_as_uint(As[m + 8][ks + tg]);
                a[mf][2] = __float_as_uint(As[m][ks + tg + 4]);
                a[mf][3] = __float_as_uint(As[m + 8][ks + tg + 4]);
            }
#pragma unroll
            for (int nf = 0; nf < 4; nf++) {
                int n = wn0 + nf * 8 + grp;
                b[nf][0] = __float_as_uint(Bs[ks + tg][n]);
                b[nf][1] = __float_as_uint(Bs[ks + tg + 4][n]);
            }
#pragma unroll
            for (int mf = 0; mf < 4; mf++)
#pragma unroll
                for (int nf = 0; nf < 4; nf++)
                    mma8(acc[mf][nf], a[mf], b[nf]);
        }
        __syncthreads();
        if (kt + 1 < KT) STOS_G();
    }
#undef LOADG_G
#undef STOS_G

#pragma unroll
    for (int mf = 0; mf < 4; mf++) {
        const int gm = m0 + wm0 + mf * 16 + grp;
#pragma unroll
        for (int nf = 0; nf < 4; nf++) {
            const int gn = n0 + wn0 + nf * 8 + tg * 2;
            const float2 bb = *(const float2*)(bias + gn);
            float2 o0 = { acc[mf][nf][0] + bb.x, acc[mf][nf][1] + bb.y };
            float2 o1 = { acc[mf][nf][2] + bb.x, acc[mf][nf][3] + bb.y };
            *(float2*)(C + (long)gm * N + gn) = o0;
            *(float2*)(C + (long)(gm + 8) * N + gn) = o1;
        }
    }
}

// ---------------- K4a: partial per-(bt,col) max/sum over 125-row slabs ----------------
__global__ __launch_bounds__(256) void k_colstats() {
    const int bt = blockIdx.x, part = blockIdx.y, c = threadIdx.x;
    const float* base = g_L + ((long)bt * NTOK + part * 125) * DIM + c;
    float m = -3.0e38f, s = 0.f;
    for (int c5 = 0; c5 < 25; c5++) {
        float v[5];
#pragma unroll
        for (int j = 0; j < 5; j++) v[j] = base[(long)(c5 * 5 + j) * DIM];
        float lm = v[0];
#pragma unroll
        for (int j = 1; j < 5; j++) lm = fmaxf(lm, v[j]);
        const float nm = fmaxf(m, lm);
        s *= __expf(m - nm);
#pragma unroll
        for (int j = 0; j < 5; j++) s += __expf(v[j] - nm);
        m = nm;
    }
    g_cmax_p[(part * BT + bt) * DIM + c] = m;
    g_csum_p[(part * BT + bt) * DIM + c] = s;
}

// ---------------- K4b: combine partials ----------------
__global__ __launch_bounds__(256) void k_colcomb() {
    const int bt = blockIdx.x, c = threadIdx.x;
    float m = -3.0e38f;
#pragma unroll
    for (int p = 0; p < 8; p++) m = fmaxf(m, g_cmax_p[(p * BT + bt) * DIM + c]);
    float s = 0.f;
#pragma unroll
    for (int p = 0; p < 8; p++)
        s += g_csum_p[(p * BT + bt) * DIM + c] * __expf(g_cmax_p[(p * BT + bt) * DIM + c] - m);
    g_colmax[bt * DIM + c] = m;
    g_colsum[bt * DIM + c] = s;
}

// ---------------- K5: v_mid[bt,h] = S1^T @ xv  (S1 = row softmax over r) ----------------
__global__ __launch_bounds__(256) void k_attmid() {
    const int bt = blockIdx.x, h = blockIdx.y;
    __shared__ float Ls[32][36];
    __shared__ float XVs[32][36];
    __shared__ float S1s[32][36];
    const int tid = threadIdx.x, warp = tid >> 5, lane = tid & 31;
    const int ln = tid >> 3, lc = (tid & 7) * 4;
    float acc[4] = {0.f, 0.f, 0.f, 0.f};
    const float4 zero4 = make_float4(0.f, 0.f, 0.f, 0.f);

    for (int ch = 0; ch < 32; ch++) {
        const int ng = ch * 32 + ln;
        const bool valid = ng < NTOK;
        const long row = ((long)bt * NTOK + ng) * DIM + h * 32 + lc;
        float4 lv  = valid ? *(const float4*)(g_L  + row) : zero4;
        float4 xvv = valid ? *(const float4*)(g_xv + row) : zero4;
        *(float4*)&Ls[ln][lc]  = lv;
        *(float4*)&XVs[ln][lc] = xvv;
        __syncthreads();
#pragma unroll
        for (int j = 0; j < 4; j++) {
            const int n = warp * 4 + j;
            const float v = Ls[n][lane];
            float mx = v;
#pragma unroll
            for (int o = 16; o; o >>= 1) mx = fmaxf(mx, __shfl_xor_sync(0xffffffffu, mx, o));
            const float e0 = __expf(v - mx);
            float sm = e0;
#pragma unroll
            for (int o = 16; o; o >>= 1) sm += __shfl_xor_sync(0xffffffffu, sm, o);
            float s1 = e0 / sm;
            if (ch * 32 + n >= NTOK) s1 = 0.f;
            S1s[n][lane] = s1;
        }
        __syncthreads();
#pragma unroll 8
        for (int n = 0; n < 32; n++) {
            const float xvb = XVs[n][lane];
#pragma unroll
            for (int j = 0; j < 4; j++) acc[j] += S1s[n][warp * 4 + j] * xvb;
        }
        __syncthreads();
    }
#pragma unroll
    for (int j = 0; j < 4; j++)
        g_vmid[(((long)bt * HN + h) * RN + warp * 4 + j) * HDIM + lane] = acc[j];
}

// ---------------- K6: S2 softmax + v_out + final combine ----------------
__global__ __launch_bounds__(256) void k_final(
    float* __restrict__ out,
    const float* __restrict__ al, const float* __restrict__ be,
    const float* __restrict__ ma, const float* __restrict__ mb)
{
    __shared__ float vm[HN * RN * HDIM];   // 8192 floats = 32KB
    __shared__ float s2s[256];
    const int bt = blockIdx.x / 50;
    const int ch = blockIdx.x % 50;
    const int tid = threadIdx.x;
    const int h = tid >> 5, d = tid & 31;
    const float sa = sigm(al[0]), sb = sigm(be[0]);
    const float sva = sigm(ma[h]), svb = sigm(mb[h]);

#pragma unroll
    for (int i = 0; i < 32; i++)
        vm[tid + i * 256] = g_vmid[(long)bt * 8192 + tid + i * 256];

    const float cm = g_colmax[bt * DIM + tid];
    const float ci = 1.f / g_colsum[bt * DIM + tid];
    __syncthreads();

    for (int t = 0; t < 20; t++) {
        const long tok = (long)bt * NTOK + ch * 20 + t;
        const long ro = tok * DIM + tid;
        const float l = g_L[ro];
        s2s[tid] = __expf(l - cm) * ci;
        __syncthreads();
        float acc = 0.f;
#pragma unroll
        for (int r = 0; r < 32; r++)
            acc += s2s[h * 32 + r] * vm[(h * 32 + r) * 32 + d];
        const float xvv = g_xv[ro];
        out[ro] = sa * g_ffn[ro] + sb * (sva * xvv + svb * acc);
        __syncthreads();
    }
}

// ---------------- launch ----------------
extern "C" void kernel_launch(void* const* d_in, const int* in_sizes, int n_in,
                              void* d_out, int out_size) {
    (void)in_sizes; (void)n_in; (void)out_size;
    const float* x     = (const float*)d_in[0];
    const float* z     = (const float*)d_in[1];
    const float* n1w   = (const float*)d_in[2];
    const float* n2w   = (const float*)d_in[3];
    const float* alpha = (const float*)d_in[4];
    const float* beta  = (const float*)d_in[5];
    const float* gamma = (const float*)d_in[6];
    const float* delta = (const float*)d_in[7];
    const float* Wq    = (const float*)d_in[8];
    const float* bq    = (const float*)d_in[9];
    const float* key   = (const float*)d_in[10];
    const float* Wv    = (const float*)d_in[11];
    const float* bv    = (const float*)d_in[12];
    const float* mha_a = (const float*)d_in[13];
    const float* mha_b = (const float*)d_in[14];
    const float* W1    = (const float*)d_in[15];
    const float* b1    = (const float*)d_in[16];
    const float* W2    = (const float*)d_in[17];
    const float* b2    = (const float*)d_in[18];
    const float* W3    = (const float*)d_in[19];
    const float* b3    = (const float*)d_in[20];
    float* out = (float*)d_out;

    k_weff<<<256, 256>>>(Wq, bq, key);
    k_norm<<<M_TOT / 8, 256>>>(x, z, n1w, n2w, gamma, delta);
    k_dualffn<<<dim3(EDIM / 64, M_TOT / 128), 256>>>(W1, b1, W2, b2);
    k_gemm<<<dim3(DIM / 128, M_TOT / 128), 256>>>(0, W3, b3, EDIM, DIM);     // ffn
    k_gemm<<<dim3(DIM / 128, M_TOT / 128), 256>>>(1, g_weff, nullptr, DIM, DIM); // L
    k_gemm<<<dim3(DIM / 128, M_TOT / 128), 256>>>(2, Wv, bv, DIM, DIM);      // xv
    k_colstats<<<dim3(BT, 8), 256>>>();
    k_colcomb<<<BT, 256>>>();
    k_attmid<<<dim3(BT, HN), 256>>>();
    k_final<<<BT * 50, 256>>>(out, alpha, beta, mha_a, mha_b);
}

// round 7
// speedup vs baseline: 1.1985x; 1.0003x over previous
#include <cuda_runtime.h>
#include <cuda_bf16.h>

// ---------------- problem constants ----------------
#define BT     96          // B*T
#define NTOK   1000        // N
#define M_TOT  96000       // B*T*N tokens
#define DIM    256         // D
#define EDIM   1024        // E = 4D
#define HN     8           // heads
#define HDIM   32          // head dim
#define RN     32          // low-rank R

// ---------------- scratch (device bss) ----------------
__device__ float g_x1[M_TOT * DIM];
__device__ float g_z1[M_TOT * DIM];
__device__ float g_G [M_TOT * EDIM];     // silu(h1)*h2
__device__ float g_ffn[M_TOT * DIM];
__device__ float g_L [M_TOT * DIM];      // attn logits, col = h*32+r
__device__ float g_xv[M_TOT * DIM];
__device__ float g_weff[DIM * DIM];
__device__ float g_abias[DIM];
__device__ float g_colmax[BT * DIM];
__device__ float g_colsum[BT * DIM];
__device__ float g_cmax_p[8 * BT * DIM];
__device__ float g_csum_p[8 * BT * DIM];
__device__ float g_vmid[BT * HN * RN * HDIM];

// ---------------- helpers ----------------
__device__ __forceinline__ float sigm(float v) { return 1.f / (1.f + __expf(-v)); }

__device__ __forceinline__ float tf32r(float f) {
    unsigned u;
    asm("cvt.rna.tf32.f32 %0, %1;" : "=r"(u) : "f"(f));
    return __uint_as_float(u);
}

__device__ __forceinline__ void mma8(float* c, const unsigned* a, const unsigned* b) {
    asm volatile(
        "mma.sync.aligned.m16n8k8.row.col.f32.tf32.tf32.f32 "
        "{%0,%1,%2,%3},{%4,%5,%6,%7},{%8,%9},{%0,%1,%2,%3};"
        : "+f"(c[0]), "+f"(c[1]), "+f"(c[2]), "+f"(c[3])
        : "r"(a[0]), "r"(a[1]), "r"(a[2]), "r"(a[3]), "r"(b[0]), "r"(b[1]));
}

// ---------------- K0: Weff = (Wq . key^T)/sqrt(HD), abias from bq ----------------
__global__ void k_weff(const float* __restrict__ Wq, const float* __restrict__ bq,
                       const float* __restrict__ key) {
    const int i = blockIdx.x;       // input channel
    const int c = threadIdx.x;      // output col = h*32 + r
    const int h = c >> 5, r = c & 31;
    const float sc = 0.17677669529663687f;   // 1/sqrt(32)
    float s = 0.f;
#pragma unroll
    for (int d = 0; d < 32; d++)
        s += Wq[i * DIM + h * 32 + d] * key[(r * HN + h) * HDIM + d];
    g_weff[i * DIM + c] = s * sc;
    if (i == 0) {
        float b = 0.f;
#pragma unroll
        for (int d = 0; d < 32; d++)
            b += bq[h * 32 + d] * key[(r * HN + h) * HDIM + d];
        g_abias[c] = b * sc;
    }
}

// ---------------- K1: fused RMSNorms (one warp = one token) ----------------
__global__ __launch_bounds__(256) void k_norm(
    const float* __restrict__ x, const float* __restrict__ z,
    const float* __restrict__ w1, const float* __restrict__ w2,
    const float* __restrict__ ga, const float* __restrict__ de)
{
    const int warp = threadIdx.x >> 5, lane = threadIdx.x & 31;
    const long tok = (long)blockIdx.x * 8 + warp;
    const float sg = sigm(ga[0]), sd = sigm(de[0]);

    const float4* xr = (const float4*)x + tok * 64;
    const float4* zr = (const float4*)z + tok * 64;
    float4 xa = xr[lane], xb = xr[lane + 32];

    float ss = xa.x*xa.x + xa.y*xa.y + xa.z*xa.z + xa.w*xa.w
             + xb.x*xb.x + xb.y*xb.y + xb.z*xb.z + xb.w*xb.w;
#pragma unroll
    for (int o = 16; o; o >>= 1) ss += __shfl_xor_sync(0xffffffffu, ss, o);
    const float r1 = rsqrtf(ss * (1.f / 256.f) + 1e-6f);

    float4 wa = ((const float4*)w1)[lane], wb = ((const float4*)w1)[lane + 32];
    float4 x1a, x1b;
    x1a.x = xa.x*r1*wa.x; x1a.y = xa.y*r1*wa.y; x1a.z = xa.z*r1*wa.z; x1a.w = xa.w*r1*wa.w;
    x1b.x = xb.x*r1*wb.x; x1b.y = xb.y*r1*wb.y; x1b.z = xb.z*r1*wb.z; x1b.w = xb.w*r1*wb.w;
    float4* x1o = (float4*)g_x1 + tok * 64;
    x1o[lane] = x1a; x1o[lane + 32] = x1b;

    float4 za = zr[lane], zb = zr[lane + 32];
    float4 ya, yb;
    ya.x = sg*x1a.x + sd*za.x; ya.y = sg*x1a.y + sd*za.y;
    ya.z = sg*x1a.z + sd*za.z; ya.w = sg*x1a.w + sd*za.w;
    yb.x = sg*x1b.x + sd*zb.x; yb.y = sg*x1b.y + sd*zb.y;
    yb.z = sg*x1b.z + sd*zb.z; yb.w = sg*x1b.w + sd*zb.w;

    float s2 = ya.x*ya.x + ya.y*ya.y + ya.z*ya.z + ya.w*ya.w
             + yb.x*yb.x + yb.y*yb.y + yb.z*yb.z + yb.w*yb.w;
#pragma unroll
    for (int o = 16; o; o >>= 1) s2 += __shfl_xor_sync(0xffffffffu, s2, o);
    const float r2 = rsqrtf(s2 * (1.f / 256.f) + 1e-6f);

    float4 va = ((const float4*)w2)[lane], vb = ((const float4*)w2)[lane + 32];
    float4 z1a, z1b;
    z1a.x = ya.x*r2*va.x; z1a.y = ya.y*r2*va.y; z1a.z = ya.z*r2*va.z; z1a.w = ya.w*r2*va.w;
    z1b.x = yb.x*r2*vb.x; z1b.y = yb.y*r2*vb.y; z1b.z = yb.z*r2*vb.z; z1b.w = yb.w*r2*vb.w;
    float4* z1o = (float4*)g_z1 + tok * 64;
    z1o[lane] = z1a; z1o[lane + 32] = z1b;
}

// ---------------- K2: dual SwiGLU GEMM: G = silu(x1@W1+b1)*(x1@W2+b2) ----------------
// block tile 128x64, 8 warps (2x4), warp tile 64x16; K step 32.
__global__ __launch_bounds__(256, 2) void k_dualffn(
    const float* __restrict__ W1, const float* __restrict__ b1,
    const float* __restrict__ W2, const float* __restrict__ b2)
{
    __shared__ float As[128][36];
    __shared__ float B1s[32][72];
    __shared__ float B2s[32][72];
    const int K = DIM, N = EDIM;
    const int tid = threadIdx.x;
    const int warp = tid >> 5, lane = tid & 31, grp = lane >> 2, tg = lane & 3;
    const int wm0 = (warp >> 2) * 64, wn0 = (warp & 3) * 16;
    const int m0 = blockIdx.y * 128, n0 = blockIdx.x * 64;

    float acc1[4][2][4], acc2[4][2][4];
#pragma unroll
    for (int a = 0; a < 4; a++)
#pragma unroll
        for (int b = 0; b < 2; b++)
#pragma unroll
            for (int c = 0; c < 4; c++) { acc1[a][b][c] = 0.f; acc2[a][b][c] = 0.f; }

    int arow[4], akq[4], brw[2], bnq[2];
#pragma unroll
    for (int i = 0; i < 4; i++) { int e = tid + i * 256; arow[i] = e >> 3; akq[i] = e & 7; }
#pragma unroll
    for (int i = 0; i < 2; i++) { int e = tid + i * 256; brw[i] = e >> 4; bnq[i] = e & 15; }

    float4 ar[4], b1r[2], b2r[2];
    const int KT = K >> 5;

#define LOADG_D(kt) do { int kb = (kt) * 32;                                              \
    _Pragma("unroll") for (int i = 0; i < 4; i++)                                         \
        ar[i] = *(const float4*)(g_x1 + (long)(m0 + arow[i]) * K + kb + akq[i] * 4);      \
    _Pragma("unroll") for (int i = 0; i < 2; i++) {                                       \
        b1r[i] = *(const float4*)(W1 + (long)(kb + brw[i]) * N + n0 + bnq[i] * 4);        \
        b2r[i] = *(const float4*)(W2 + (long)(kb + brw[i]) * N + n0 + bnq[i] * 4); } } while (0)

#define STOS_D() do {                                                                     \
    _Pragma("unroll") for (int i = 0; i < 4; i++) { float4 v = ar[i];                     \
        v.x = tf32r(v.x); v.y = tf32r(v.y); v.z = tf32r(v.z); v.w = tf32r(v.w);           \
        *(float4*)&As[arow[i]][akq[i] * 4] = v; }                                         \
    _Pragma("unroll") for (int i = 0; i < 2; i++) { float4 u = b1r[i], w = b2r[i];        \
        u.x = tf32r(u.x); u.y = tf32r(u.y); u.z = tf32r(u.z); u.w = tf32r(u.w);           \
        w.x = tf32r(w.x); w.y = tf32r(w.y); w.z = tf32r(w.z); w.w = tf32r(w.w);           \
        *(float4*)&B1s[brw[i]][bnq[i] * 4] = u;                                           \
        *(float4*)&B2s[brw[i]][bnq[i] * 4] = w; } } while (0)

    LOADG_D(0); STOS_D();
    for (int kt = 0; kt < KT; kt++) {
        __syncthreads();
        if (kt + 1 < KT) LOADG_D(kt + 1);
#pragma unroll
        for (int kk = 0; kk < 4; kk++) {
            const int ks = kk * 8;
            unsigned a[4][4], bb1[2][2], bb2[2][2];
#pragma unroll
            for (int mf = 0; mf < 4; mf++) {
                int m = wm0 + mf * 16 + grp;
                a[mf][0] = __float_as_uint(As[m][ks + tg]);
                a[mf][1] = __float_as_uint(As[m + 8][ks + tg]);
                a[mf][2] = __float_as_uint(As[m][ks + tg + 4]);
                a[mf][3] = __float_as_uint(As[m + 8][ks + tg + 4]);
            }
#pragma unroll
            for (int nf = 0; nf < 2; nf++) {
                int n = wn0 + nf * 8 + grp;
                bb1[nf][0] = __float_as_uint(B1s[ks + tg][n]);
                bb1[nf][1] = __float_as_uint(B1s[ks + tg + 4][n]);
                bb2[nf][0] = __float_as_uint(B2s[ks + tg][n]);
                bb2[nf][1] = __float_as_uint(B2s[ks + tg + 4][n]);
            }
#pragma unroll
            for (int mf = 0; mf < 4; mf++)
#pragma unroll
                for (int nf = 0; nf < 2; nf++) {
                    mma8(acc1[mf][nf], a[mf], bb1[nf]);
                    mma8(acc2[mf][nf], a[mf], bb2[nf]);
                }
        }
        __syncthreads();
        if (kt + 1 < KT) STOS_D();
    }
#undef LOADG_D
#undef STOS_D

#pragma unroll
    for (int mf = 0; mf < 4; mf++) {
        const int gm = m0 + wm0 + mf * 16 + grp;
#pragma unroll
        for (int nf = 0; nf < 2; nf++) {
            const int gn = n0 + wn0 + nf * 8 + tg * 2;
            const float c1x = b1[gn], c1y = b1[gn + 1];
            const float c2x = b2[gn], c2y = b2[gn + 1];
            float h1, h2;
            float2 o0, o1;
            h1 = acc1[mf][nf][0] + c1x; h2 = acc2[mf][nf][0] + c2x; o0.x = h1 * sigm(h1) * h2;
            h1 = acc1[mf][nf][1] + c1y; h2 = acc2[mf][nf][1] + c2y; o0.y = h1 * sigm(h1) * h2;
            h1 = acc1[mf][nf][2] + c1x; h2 = acc2[mf][nf][2] + c2x; o1.x = h1 * sigm(h1) * h2;
            h1 = acc1[mf][nf][3] + c1y; h2 = acc2[mf][nf][3] + c2y; o1.y = h1 * sigm(h1) * h2;
            *(float2*)(g_G + (long)gm * EDIM + gn) = o0;
            *(float2*)(g_G + (long)(gm + 8) * EDIM + gn) = o1;
        }
    }
}

// ---------------- K3: generic GEMM C = A@W + bias, 128x128 tile ----------------
// mode 0: A=g_G,  C=g_ffn, bias=ext (b3)
// mode 1: A=g_z1, C=g_L,   bias=g_abias
// mode 2: A=g_x1, C=g_xv,  bias=ext (bv)
__global__ __launch_bounds__(256, 2) void k_gemm(
    int mode, const float* __restrict__ W, const float* __restrict__ biasExt,
    int K, int N)
{
    const float* __restrict__ A = (mode == 0) ? g_G : (mode == 1) ? g_z1 : g_x1;
    float* __restrict__ C = (mode == 0) ? g_ffn : (mode == 1) ? g_L : g_xv;
    const float* __restrict__ bias = (mode == 1) ? g_abias : biasExt;

    __shared__ float As[128][36];
    __shared__ float Bs[32][136];
    const int tid = threadIdx.x;
    const int warp = tid >> 5, lane = tid & 31, grp = lane >> 2, tg = lane & 3;
    const int wm0 = (warp >> 2) * 64, wn0 = (warp & 3) * 32;
    const int m0 = blockIdx.y * 128, n0 = blockIdx.x * 128;

    float acc[4][4][4];
#pragma unroll
    for (int a = 0; a < 4; a++)
#pragma unroll
        for (int b = 0; b < 4; b++)
#pragma unroll
            for (int c = 0; c < 4; c++) acc[a][b][c] = 0.f;

    int arow[4], akq[4], brw[4], bnq[4];
#pragma unroll
    for (int i = 0; i < 4; i++) {
        int e = tid + i * 256;
        arow[i] = e >> 3; akq[i] = e & 7;
        brw[i] = e >> 5;  bnq[i] = e & 31;
    }

    float4 ar[4], br[4];
    const int KT = K >> 5;

#define LOADG_G(kt) do { int kb = (kt) * 32;                                              \
    _Pragma("unroll") for (int i = 0; i < 4; i++)                                         \
        ar[i] = *(const float4*)(A + (long)(m0 + arow[i]) * K + kb + akq[i] * 4);         \
    _Pragma("unroll") for (int i = 0; i < 4; i++)                                         \
        br[i] = *(const float4*)(W + (long)(kb + brw[i]) * N + n0 + bnq[i] * 4); } while (0)

#define STOS_G() do {                                                                     \
    _Pragma("unroll") for (int i = 0; i < 4; i++) { float4 v = ar[i];                     \
        v.x = tf32r(v.x); v.y = tf32r(v.y); v.z = tf32r(v.z); v.w = tf32r(v.w);           \
        *(float4*)&As[arow[i]][akq[i] * 4] = v;                                           \
        float4 u = br[i];                                                                 \
        u.x = tf32r(u.x); u.y = tf32r(u.y); u.z = tf32r(u.z); u.w = tf32r(u.w);           \
        *(float4*)&Bs[brw[i]][bnq[i] * 4] = u; } } while (0)

    LOADG_G(0); STOS_G();
    for (int kt = 0; kt < KT; kt++) {
        __syncthreads();
        if (kt + 1 < KT) LOADG_G(kt + 1);
#pragma unroll
        for (int kk = 0; kk < 4; kk++) {
            const int ks = kk * 8;
            unsigned a[4][4], b[4][2];
#pragma unroll
            for (int mf = 0; mf < 4; mf++) {
                int m = wm0 + mf * 16 + grp;
                a[mf][0] = __float_as_uint(As[m][ks + tg]);
                a[mf][1] = __float_as_uint(As[m + 8][ks + tg]);
                a[mf][2] = __float_as_uint(As[m][ks + tg + 4]);
                a[mf][3] = __float_as_uint(As[m + 8][ks + tg + 4]);
            }
#pragma unroll
            for (int nf = 0; nf < 4; nf++) {
                int n = wn0 + nf * 8 + grp;
                b[nf][0] = __float_as_uint(Bs[ks + tg][n]);
                b[nf][1] = __float_as_uint(Bs[ks + tg + 4][n]);
            }
#pragma unroll
            for (int mf = 0; mf < 4; mf++)
#pragma unroll
                for (int nf = 0; nf < 4; nf++)
                    mma8(acc[mf][nf], a[mf], b[nf]);
        }
        __syncthreads();
        if (kt + 1 < KT) STOS_G();
    }
#undef LOADG_G
#undef STOS_G

#pragma unroll
    for (int mf = 0; mf < 4; mf++) {
        const int gm = m0 + wm0 + mf * 16 + grp;
#pragma unroll
        for (int nf = 0; nf < 4; nf++) {
            const int gn = n0 + wn0 + nf * 8 + tg * 2;
            const float2 bb = *(const float2*)(bias + gn);
            float2 o0 = { acc[mf][nf][0] + bb.x, acc[mf][nf][1] + bb.y };
            float2 o1 = { acc[mf][nf][2] + bb.x, acc[mf][nf][3] + bb.y };
            *(float2*)(C + (long)gm * N + gn) = o0;
            *(float2*)(C + (long)(gm + 8) * N + gn) = o1;
        }
    }
}

// ---------------- K4a: partial per-(bt,col) max/sum over 125-row slabs ----------------
__global__ __launch_bounds__(256) void k_colstats() {
    const int bt = blockIdx.x, part = blockIdx.y, c = threadIdx.x;
    const float* base = g_L + ((long)bt * NTOK + part * 125) * DIM + c;
    float m = -3.0e38f, s = 0.f;
    for (int c5 = 0; c5 < 25; c5++) {
        float v[5];
#pragma unroll
        for (int j = 0; j < 5; j++) v[j] = base[(long)(c5 * 5 + j) * DIM];
        float lm = v[0];
#pragma unroll
        for (int j = 1; j < 5; j++) lm = fmaxf(lm, v[j]);
        const float nm = fmaxf(m, lm);
        s *= __expf(m - nm);
#pragma unroll
        for (int j = 0; j < 5; j++) s += __expf(v[j] - nm);
        m = nm;
    }
    g_cmax_p[(part * BT + bt) * DIM + c] = m;
    g_csum_p[(part * BT + bt) * DIM + c] = s;
}

// ---------------- K4b: combine partials ----------------
__global__ __launch_bounds__(256) void k_colcomb() {
    const int bt = blockIdx.x, c = threadIdx.x;
    float m = -3.0e38f;
#pragma unroll
    for (int p = 0; p < 8; p++) m = fmaxf(m, g_cmax_p[(p * BT + bt) * DIM + c]);
    float s = 0.f;
#pragma unroll
    for (int p = 0; p < 8; p++)
        s += g_csum_p[(p * BT + bt) * DIM + c] * __expf(g_cmax_p[(p * BT + bt) * DIM + c] - m);
    g_colmax[bt * DIM + c] = m;
    g_colsum[bt * DIM + c] = s;
}

// ---------------- K5: v_mid[bt,h] = S1^T @ xv  (S1 = row softmax over r) ----------------
__global__ __launch_bounds__(256) void k_attmid() {
    const int bt = blockIdx.x, h = blockIdx.y;
    __shared__ float Ls[32][36];
    __shared__ float XVs[32][36];
    __shared__ float S1s[32][36];
    const int tid = threadIdx.x, warp = tid >> 5, lane = tid & 31;
    const int ln = tid >> 3, lc = (tid & 7) * 4;
    float acc[4] = {0.f, 0.f, 0.f, 0.f};
    const float4 zero4 = make_float4(0.f, 0.f, 0.f, 0.f);

    for (int ch = 0; ch < 32; ch++) {
        const int ng = ch * 32 + ln;
        const bool valid = ng < NTOK;
        const long row = ((long)bt * NTOK + ng) * DIM + h * 32 + lc;
        float4 lv  = valid ? *(const float4*)(g_L  + row) : zero4;
        float4 xvv = valid ? *(const float4*)(g_xv + row) : zero4;
        *(float4*)&Ls[ln][lc]  = lv;
        *(float4*)&XVs[ln][lc] = xvv;
        __syncthreads();
#pragma unroll
        for (int j = 0; j < 4; j++) {
            const int n = warp * 4 + j;
            const float v = Ls[n][lane];
            float mx = v;
#pragma unroll
            for (int o = 16; o; o >>= 1) mx = fmaxf(mx, __shfl_xor_sync(0xffffffffu, mx, o));
            const float e0 = __expf(v - mx);
            float sm = e0;
#pragma unroll
            for (int o = 16; o; o >>= 1) sm += __shfl_xor_sync(0xffffffffu, sm, o);
            float s1 = e0 / sm;
            if (ch * 32 + n >= NTOK) s1 = 0.f;
            S1s[n][lane] = s1;
        }
        __syncthreads();
#pragma unroll 8
        for (int n = 0; n < 32; n++) {
            const float xvb = XVs[n][lane];
#pragma unroll
            for (int j = 0; j < 4; j++) acc[j] += S1s[n][warp * 4 + j] * xvb;
        }
        __syncthreads();
    }
#pragma unroll
    for (int j = 0; j < 4; j++)
        g_vmid[(((long)bt * HN + h) * RN + warp * 4 + j) * HDIM + lane] = acc[j];
}

// ---------------- K6: S2 softmax + v_out + final combine ----------------
__global__ __launch_bounds__(256) void k_final(
    float* __restrict__ out,
    const float* __restrict__ al, const float* __restrict__ be,
    const float* __restrict__ ma, const float* __restrict__ mb)
{
    __shared__ float vm[HN * RN * HDIM];   // 8192 floats = 32KB
    __shared__ float s2s[256];
    const int bt = blockIdx.x / 50;
    const int ch = blockIdx.x % 50;
    const int tid = threadIdx.x;
    const int h = tid >> 5, d = tid & 31;
    const float sa = sigm(al[0]), sb = sigm(be[0]);
    const float sva = sigm(ma[h]), svb = sigm(mb[h]);

#pragma unroll
    for (int i = 0; i < 32; i++)
        vm[tid + i * 256] = g_vmid[(long)bt * 8192 + tid + i * 256];

    const float cm = g_colmax[bt * DIM + tid];
    const float ci = 1.f / g_colsum[bt * DIM + tid];
    __syncthreads();

    for (int t = 0; t < 20; t++) {
        const long tok = (long)bt * NTOK + ch * 20 + t;
        const long ro = tok * DIM + tid;
        const float l = g_L[ro];
        s2s[tid] = __expf(l - cm) * ci;
        __syncthreads();
        float acc = 0.f;
#pragma unroll
        for (int r = 0; r < 32; r++)
            acc += s2s[h * 32 + r] * vm[(h * 32 + r) * 32 + d];
        const float xvv = g_xv[ro];
        out[ro] = sa * g_ffn[ro] + sb * (sva * xvv + svb * acc);
        __syncthreads();
    }
}

// ---------------- launch ----------------
extern "C" void kernel_launch(void* const* d_in, const int* in_sizes, int n_in,
                              void* d_out, int out_size) {
    (void)in_sizes; (void)n_in; (void)out_size;
    const float* x     = (const float*)d_in[0];
    const float* z     = (const float*)d_in[1];
    const float* n1w   = (const float*)d_in[2];
    const float* n2w   = (const float*)d_in[3];
    const float* alpha = (const float*)d_in[4];
    const float* beta  = (const float*)d_in[5];
    const float* gamma = (const float*)d_in[6];
    const float* delta = (const float*)d_in[7];
    const float* Wq    = (const float*)d_in[8];
    const float* bq    = (const float*)d_in[9];
    const float* key   = (const float*)d_in[10];
    const float* Wv    = (const float*)d_in[11];
    const float* bv    = (const float*)d_in[12];
    const float* mha_a = (const float*)d_in[13];
    const float* mha_b = (const float*)d_in[14];
    const float* W1    = (const float*)d_in[15];
    const float* b1    = (const float*)d_in[16];
    const float* W2    = (const float*)d_in[17];
    const float* b2    = (const float*)d_in[18];
    const float* W3    = (const float*)d_in[19];
    const float* b3    = (const float*)d_in[20];
    float* out = (float*)d_out;

    k_weff<<<256, 256>>>(Wq, bq, key);
    k_norm<<<M_TOT / 8, 256>>>(x, z, n1w, n2w, gamma, delta);
    k_dualffn<<<dim3(EDIM / 64, M_TOT / 128), 256>>>(W1, b1, W2, b2);
    k_gemm<<<dim3(DIM / 128, M_TOT / 128), 256>>>(0, W3, b3, EDIM, DIM);     // ffn
    k_gemm<<<dim3(DIM / 128, M_TOT / 128), 256>>>(1, g_weff, nullptr, DIM, DIM); // L
    k_gemm<<<dim3(DIM / 128, M_TOT / 128), 256>>>(2, Wv, bv, DIM, DIM);      // xv
    k_colstats<<<dim3(BT, 8), 256>>>();
    k_colcomb<<<BT, 256>>>();
    k_attmid<<<dim3(BT, HN), 256>>>();
    k_final<<<BT * 50, 256>>>(out, alpha, beta, mha_a, mha_b);
}

// round 11
// speedup vs baseline: 1.6015x; 1.3362x over previous
#include <cuda_runtime.h>
#include <cstdint>

// ---------------- problem constants ----------------
#define BT     96
#define NTOK   1000
#define M_TOT  96000
#define DIM    256
#define EDIM   1024
#define HN     8
#define HDIM   32
#define RN     32

// ---------------- scratch (device bss) ----------------
__device__ float g_x1[M_TOT * DIM];
__device__ float g_z1[M_TOT * DIM];
__device__ float g_G [M_TOT * EDIM];
__device__ float g_ffn[M_TOT * DIM];
__device__ float g_L [M_TOT * DIM];
__device__ float g_xv[M_TOT * DIM];
__device__ float g_wefft[DIM * DIM];     // [n=256][k=256], tf32-rounded
__device__ float g_abias[DIM];
__device__ float g_colmax[BT * DIM];
__device__ float g_colsum[BT * DIM];
__device__ float g_cmax_p[8 * BT * DIM];
__device__ float g_csum_p[8 * BT * DIM];
__device__ float g_vmid[BT * HN * RN * HDIM];
// pre-transposed, tf32-rounded weights [n][k]
__device__ float g_W1t[EDIM * DIM];
__device__ float g_W2t[EDIM * DIM];
__device__ float g_W3t[DIM * EDIM];
__device__ float g_Wvt[DIM * DIM];

// ---------------- helpers ----------------
__device__ __forceinline__ float sigm(float v) { return 1.f / (1.f + __expf(-v)); }
__device__ __forceinline__ float tf32r(float f) {
    unsigned u; asm("cvt.rna.tf32.f32 %0, %1;" : "=r"(u) : "f"(f));
    return __uint_as_float(u);
}
__device__ __forceinline__ uint32_t smem_u32(const void* p) {
    uint32_t a;
    asm("{ .reg .u64 t; cvta.to.shared.u64 t, %1; cvt.u32.u64 %0, t; }" : "=r"(a) : "l"(p));
    return a;
}
__device__ __forceinline__ void mma8(float* c, const unsigned* a, const unsigned* b) {
    asm volatile(
        "mma.sync.aligned.m16n8k8.row.col.f32.tf32.tf32.f32 "
        "{%0,%1,%2,%3},{%4,%5,%6,%7},{%8,%9},{%0,%1,%2,%3};"
        : "+f"(c[0]), "+f"(c[1]), "+f"(c[2]), "+f"(c[3])
        : "r"(a[0]), "r"(a[1]), "r"(a[2]), "r"(a[3]), "r"(b[0]), "r"(b[1]));
}
// ldmatrix x4 of 32-bit data (b16 path moves raw bits; per-matrix layout = 8 rows x 4 words,
// thread t <- (row t/4, word t%4), exactly the tf32 m16n8k8 fragment geometry)
__device__ __forceinline__ void ldm4(uint32_t addr, unsigned* r) {
    asm volatile("ldmatrix.sync.aligned.m8n8.x4.shared.b16 {%0,%1,%2,%3}, [%4];"
        : "=r"(r[0]), "=r"(r[1]), "=r"(r[2]), "=r"(r[3]) : "r"(addr));
}

// ---------------- K_prept: dst[n*K+k] = tf32r(src[k*N+n]); dst resolved DEVICE-SIDE ----------------
__global__ void k_prept(const float* __restrict__ src, int which, int K, int N) {
    float* __restrict__ dst = (which == 0) ? g_W1t : (which == 1) ? g_W2t
                            : (which == 2) ? g_W3t : g_Wvt;
    __shared__ float t[32][33];
    const int k0 = blockIdx.x * 32, n0 = blockIdx.y * 32;
    for (int i = threadIdx.y; i < 32; i += 8)
        t[i][threadIdx.x] = src[(long)(k0 + i) * N + n0 + threadIdx.x];
    __syncthreads();
    for (int i = threadIdx.y; i < 32; i += 8)
        dst[(long)(n0 + i) * K + k0 + threadIdx.x] = tf32r(t[threadIdx.x][i]);
}

// ---------------- K0: wefft[n][k] (device-side write) + abias ----------------
__global__ void k_weff(const float* __restrict__ Wq, const float* __restrict__ bq,
                       const float* __restrict__ key) {
    const int i = blockIdx.x;       // k (input channel)
    const int c = threadIdx.x;      // n (output col = h*32 + r)
    const int h = c >> 5, r = c & 31;
    const float sc = 0.17677669529663687f;
    float s = 0.f;
#pragma unroll
    for (int d = 0; d < 32; d++)
        s += Wq[i * DIM + h * 32 + d] * key[(r * HN + h) * HDIM + d];
    g_wefft[c * DIM + i] = tf32r(s * sc);
    if (i == 0) {
        float b = 0.f;
#pragma unroll
        for (int d = 0; d < 32; d++)
            b += bq[h * 32 + d] * key[(r * HN + h) * HDIM + d];
        g_abias[c] = b * sc;
    }
}

// ---------------- K1: fused RMSNorms (R6-passing version) ----------------
__global__ __launch_bounds__(256) void k_norm(
    const float* __restrict__ x, const float* __restrict__ z,
    const float* __restrict__ w1, const float* __restrict__ w2,
    const float* __restrict__ ga, const float* __restrict__ de)
{
    const int warp = threadIdx.x >> 5, lane = threadIdx.x & 31;
    const long tok = (long)blockIdx.x * 8 + warp;
    const float sg = sigm(ga[0]), sd = sigm(de[0]);

    const float4* xr = (const float4*)x + tok * 64;
    const float4* zr = (const float4*)z + tok * 64;
    float4 xa = xr[lane], xb = xr[lane + 32];

    float ss = xa.x*xa.x + xa.y*xa.y + xa.z*xa.z + xa.w*xa.w
             + xb.x*xb.x + xb.y*xb.y + xb.z*xb.z + xb.w*xb.w;
#pragma unroll
    for (int o = 16; o; o >>= 1) ss += __shfl_xor_sync(0xffffffffu, ss, o);
    const float r1 = rsqrtf(ss * (1.f / 256.f) + 1e-6f);

    float4 wa = ((const float4*)w1)[lane], wb = ((const float4*)w1)[lane + 32];
    float4 x1a, x1b;
    x1a.x = xa.x*r1*wa.x; x1a.y = xa.y*r1*wa.y; x1a.z = xa.z*r1*wa.z; x1a.w = xa.w*r1*wa.w;
    x1b.x = xb.x*r1*wb.x; x1b.y = xb.y*r1*wb.y; x1b.z = xb.z*r1*wb.z; x1b.w = xb.w*r1*wb.w;
    float4* x1o = (float4*)g_x1 + tok * 64;
    x1o[lane] = x1a; x1o[lane + 32] = x1b;

    float4 za = zr[lane], zb = zr[lane + 32];
    float4 ya, yb;
    ya.x = sg*x1a.x + sd*za.x; ya.y = sg*x1a.y + sd*za.y;
    ya.z = sg*x1a.z + sd*za.z; ya.w = sg*x1a.w + sd*za.w;
    yb.x = sg*x1b.x + sd*zb.x; yb.y = sg*x1b.y + sd*zb.y;
    yb.z = sg*x1b.z + sd*zb.z; yb.w = sg*x1b.w + sd*zb.w;

    float s2 = ya.x*ya.x + ya.y*ya.y + ya.z*ya.z + ya.w*ya.w
             + yb.x*yb.x + yb.y*yb.y + yb.z*yb.z + yb.w*yb.w;
#pragma unroll
    for (int o = 16; o; o >>= 1) s2 += __shfl_xor_sync(0xffffffffu, s2, o);
    const float r2 = rsqrtf(s2 * (1.f / 256.f) + 1e-6f);

    float4 va = ((const float4*)w2)[lane], vb = ((const float4*)w2)[lane + 32];
    float4 z1a, z1b;
    z1a.x = ya.x*r2*va.x; z1a.y = ya.y*r2*va.y; z1a.z = ya.z*r2*va.z; z1a.w = ya.w*r2*va.w;
    z1b.x = yb.x*r2*vb.x; z1b.y = yb.y*r2*vb.y; z1b.z = yb.z*r2*vb.z; z1b.w = yb.w*r2*vb.w;
    float4* z1o = (float4*)g_z1 + tok * 64;
    z1o[lane] = z1a; z1o[lane + 32] = z1b;
}

// ---------------- K2: dual SwiGLU GEMM (ldmatrix operand path) ----------------
// block tile 128(M) x 64(N per matrix), 8 warps (2x4), warp tile 64x16 per matrix; K-step 32.
__global__ __launch_bounds__(256, 2) void k_dualffn(
    const float* __restrict__ b1, const float* __restrict__ b2)
{
    __shared__ __align__(16) float As[128][36];
    __shared__ __align__(16) float B1s[64][36];
    __shared__ __align__(16) float B2s[64][36];
    const int K = DIM;
    const int tid = threadIdx.x;
    const int warp = tid >> 5, lane = tid & 31, grp = lane >> 2, tg = lane & 3;
    const int wm0 = (warp >> 2) * 64, wn0 = (warp & 3) * 16;
    const int m0 = blockIdx.y * 128, n0 = blockIdx.x * 64;

    float acc1[4][2][4], acc2[4][2][4];
#pragma unroll
    for (int a = 0; a < 4; a++)
#pragma unroll
        for (int b = 0; b < 2; b++)
#pragma unroll
            for (int c = 0; c < 4; c++) { acc1[a][b][c] = 0.f; acc2[a][b][c] = 0.f; }

    int arow[4], brw[2];
    const int acol = (tid & 7) * 4;
#pragma unroll
    for (int i = 0; i < 4; i++) arow[i] = (tid + i * 256) >> 3;
#pragma unroll
    for (int i = 0; i < 2; i++) brw[i] = (tid + i * 256) >> 3;

    // ldmatrix lane geometry: lanes 0-7 -> rows +0 col 0 | 8-15 -> rows +8 col 0
    //                         lanes 16-23 -> rows +0 col 4 | 24-31 -> rows +8 col 4
    const int lrow = (lane & 7) + ((lane >> 3) & 1) * 8;
    const int lcol = (lane >> 4) * 4;
    const uint32_t aAd  = smem_u32(&As[0][0])  + (uint32_t)(((wm0 + lrow) * 36 + lcol) * 4);
    const uint32_t b1Ad = smem_u32(&B1s[0][0]) + (uint32_t)(((wn0 + lrow) * 36 + lcol) * 4);
    const uint32_t b2Ad = smem_u32(&B2s[0][0]) + (uint32_t)(((wn0 + lrow) * 36 + lcol) * 4);

    float4 ar[4], b1r[2], b2r[2];
    const int KT = K >> 5;

#define LOADG_D(kt) do { int kb = (kt) * 32;                                               \
    _Pragma("unroll") for (int i = 0; i < 4; i++)                                          \
        ar[i] = *(const float4*)(g_x1 + (long)(m0 + arow[i]) * K + kb + acol);             \
    _Pragma("unroll") for (int i = 0; i < 2; i++) {                                        \
        b1r[i] = *(const float4*)(g_W1t + (long)(n0 + brw[i]) * K + kb + acol);            \
        b2r[i] = *(const float4*)(g_W2t + (long)(n0 + brw[i]) * K + kb + acol); } } while (0)

#define STOS_D() do {                                                                      \
    _Pragma("unroll") for (int i = 0; i < 4; i++) { float4 v = ar[i];                      \
        v.x = tf32r(v.x); v.y = tf32r(v.y); v.z = tf32r(v.z); v.w = tf32r(v.w);            \
        *(float4*)&As[arow[i]][acol] = v; }                                                \
    _Pragma("unroll") for (int i = 0; i < 2; i++) {                                        \
        *(float4*)&B1s[brw[i]][acol] = b1r[i];                                             \
        *(float4*)&B2s[brw[i]][acol] = b2r[i]; } } while (0)

    LOADG_D(0); STOS_D();
    for (int kt = 0; kt < KT; kt++) {
        __syncthreads();
        if (kt + 1 < KT) LOADG_D(kt + 1);
#pragma unroll
        for (int kk = 0; kk < 4; kk++) {
            const uint32_t ks4 = kk * 32;   // 8 floats * 4B
            unsigned a[4][4], bb1[2][2], bb2[2][2], t[4];
#pragma unroll
            for (int mf = 0; mf < 4; mf++) ldm4(aAd + mf * 2304 + ks4, a[mf]);
            ldm4(b1Ad + ks4, t);
            bb1[0][0] = t[0]; bb1[1][0] = t[1]; bb1[0][1] = t[2]; bb1[1][1] = t[3];
            ldm4(b2Ad + ks4, t);
            bb2[0][0] = t[0]; bb2[1][0] = t[1]; bb2[0][1] = t[2]; bb2[1][1] = t[3];
#pragma unroll
            for (int mf = 0; mf < 4; mf++)
#pragma unroll
                for (int nf = 0; nf < 2; nf++) {
                    mma8(acc1[mf][nf], a[mf], bb1[nf]);
                    mma8(acc2[mf][nf], a[mf], bb2[nf]);
                }
        }
        __syncthreads();
        if (kt + 1 < KT) STOS_D();
    }
#undef LOADG_D
#undef STOS_D

#pragma unroll
    for (int mf = 0; mf < 4; mf++) {
        const int gm = m0 + wm0 + mf * 16 + grp;
#pragma unroll
        for (int nf = 0; nf < 2; nf++) {
            const int gn = n0 + wn0 + nf * 8 + tg * 2;
            const float c1x = b1[gn], c1y = b1[gn + 1];
            const float c2x = b2[gn], c2y = b2[gn + 1];
            float h1, h2;
            float2 o0, o1;
            h1 = acc1[mf][nf][0] + c1x; h2 = acc2[mf][nf][0] + c2x; o0.x = h1 * sigm(h1) * h2;
            h1 = acc1[mf][nf][1] + c1y; h2 = acc2[mf][nf][1] + c2y; o0.y = h1 * sigm(h1) * h2;
            h1 = acc1[mf][nf][2] + c1x; h2 = acc2[mf][nf][2] + c2x; o1.x = h1 * sigm(h1) * h2;
            h1 = acc1[mf][nf][3] + c1y; h2 = acc2[mf][nf][3] + c2y; o1.y = h1 * sigm(h1) * h2;
            *(float2*)(g_G + (long)gm * EDIM + gn) = o0;
            *(float2*)(g_G + (long)(gm + 8) * EDIM + gn) = o1;
        }
    }
}

// ---------------- K3: generic GEMM C = A@W^T + bias (W pre-transposed [n][k]) ----------------
// mode 0: A=g_G,  Wt=g_W3t,   C=g_ffn, bias=b3      (K=1024)
// mode 1: A=g_z1, Wt=g_wefft, C=g_L,   bias=g_abias (K=256)
// mode 2: A=g_x1, Wt=g_Wvt,   C=g_xv,  bias=bv      (K=256)
__global__ __launch_bounds__(256, 2) void k_gemm(
    int mode, const float* __restrict__ biasExt, int K, int N)
{
    const float* __restrict__ A  = (mode == 0) ? g_G : (mode == 1) ? g_z1 : g_x1;
    const float* __restrict__ Wt = (mode == 0) ? g_W3t : (mode == 1) ? g_wefft : g_Wvt;
    float* __restrict__ C = (mode == 0) ? g_ffn : (mode == 1) ? g_L : g_xv;
    const float* __restrict__ bias = (mode == 1) ? g_abias : biasExt;

    __shared__ __align__(16) float As[128][36];
    __shared__ __align__(16) float Bs[128][36];
    const int tid = threadIdx.x;
    const int warp = tid >> 5, lane = tid & 31, grp = lane >> 2, tg = lane & 3;
    const int wm0 = (warp >> 2) * 64, wn0 = (warp & 3) * 32;
    const int m0 = blockIdx.y * 128, n0 = blockIdx.x * 128;

    float acc[4][4][4];
#pragma unroll
    for (int a = 0; a < 4; a++)
#pragma unroll
        for (int b = 0; b < 4; b++)
#pragma unroll
            for (int c = 0; c < 4; c++) acc[a][b][c] = 0.f;

    int arow[4];
    const int acol = (tid & 7) * 4;
#pragma unroll
    for (int i = 0; i < 4; i++) arow[i] = (tid + i * 256) >> 3;

    const int lrow = (lane & 7) + ((lane >> 3) & 1) * 8;
    const int lcol = (lane >> 4) * 4;
    const uint32_t aAd = smem_u32(&As[0][0]) + (uint32_t)(((wm0 + lrow) * 36 + lcol) * 4);
    const uint32_t bAd = smem_u32(&Bs[0][0]) + (uint32_t)(((wn0 + lrow) * 36 + lcol) * 4);

    float4 ar[4], br[4];
    const int KT = K >> 5;

#define LOADG_G(kt) do { int kb = (kt) * 32;                                               \
    _Pragma("unroll") for (int i = 0; i < 4; i++) {                                        \
        ar[i] = *(const float4*)(A  + (long)(m0 + arow[i]) * K + kb + acol);               \
        br[i] = *(const float4*)(Wt + (long)(n0 + arow[i]) * K + kb + acol); } } while (0)

#define STOS_G() do {                                                                      \
    _Pragma("unroll") for (int i = 0; i < 4; i++) { float4 v = ar[i];                      \
        v.x = tf32r(v.x); v.y = tf32r(v.y); v.z = tf32r(v.z); v.w = tf32r(v.w);            \
        *(float4*)&As[arow[i]][acol] = v;                                                  \
        *(float4*)&Bs[arow[i]][acol] = br[i]; } } while (0)

    LOADG_G(0); STOS_G();
    for (int kt = 0; kt < KT; kt++) {
        __syncthreads();
        if (kt + 1 < KT) LOADG_G(kt + 1);
#pragma unroll
        for (int kk = 0; kk < 4; kk++) {
            const uint32_t ks4 = kk * 32;
            unsigned a[4][4], b[4][2], t[4];
#pragma unroll
            for (int mf = 0; mf < 4; mf++) ldm4(aAd + mf * 2304 + ks4, a[mf]);
            ldm4(bAd + ks4, t);
            b[0][0] = t[0]; b[1][0] = t[1]; b[0][1] = t[2]; b[1][1] = t[3];
            ldm4(bAd + 2304 + ks4, t);
            b[2][0] = t[0]; b[3][0] = t[1]; b[2][1] = t[2]; b[3][1] = t[3];
#pragma unroll
            for (int mf = 0; mf < 4; mf++)
#pragma unroll
                for (int nf = 0; nf < 4; nf++)
                    mma8(acc[mf][nf], a[mf], b[nf]);
        }
        __syncthreads();
        if (kt + 1 < KT) STOS_G();
    }
#undef LOADG_G
#undef STOS_G

#pragma unroll
    for (int mf = 0; mf < 4; mf++) {
        const int gm = m0 + wm0 + mf * 16 + grp;
#pragma unroll
        for (int nf = 0; nf < 4; nf++) {
            const int gn = n0 + wn0 + nf * 8 + tg * 2;
            const float2 bb = *(const float2*)(bias + gn);
            float2 o0 = { acc[mf][nf][0] + bb.x, acc[mf][nf][1] + bb.y };
            float2 o1 = { acc[mf][nf][2] + bb.x, acc[mf][nf][3] + bb.y };
            *(float2*)(C + (long)gm * N + gn) = o0;
            *(float2*)(C + (long)(gm + 8) * N + gn) = o1;
        }
    }
}

// ---------------- K4a: partial per-(bt,col) max/sum over 125-row slabs ----------------
__global__ __launch_bounds__(256) void k_colstats() {
    const int bt = blockIdx.x, part = blockIdx.y, c = threadIdx.x;
    const float* base = g_L + ((long)bt * NTOK + part * 125) * DIM + c;
    float m = -3.0e38f, s = 0.f;
    for (int c5 = 0; c5 < 25; c5++) {
        float v[5];
#pragma unroll
        for (int j = 0; j < 5; j++) v[j] = base[(long)(c5 * 5 + j) * DIM];
        float lm = v[0];
#pragma unroll
        for (int j = 1; j < 5; j++) lm = fmaxf(lm, v[j]);
        const float nm = fmaxf(m, lm);
        s *= __expf(m - nm);
#pragma unroll
        for (int j = 0; j < 5; j++) s += __expf(v[j] - nm);
        m = nm;
    }
    g_cmax_p[(part * BT + bt) * DIM + c] = m;
    g_csum_p[(part * BT + bt) * DIM + c] = s;
}

// ---------------- K4b: combine partials ----------------
__global__ __launch_bounds__(256) void k_colcomb() {
    const int bt = blockIdx.x, c = threadIdx.x;
    float m = -3.0e38f;
#pragma unroll
    for (int p = 0; p < 8; p++) m = fmaxf(m, g_cmax_p[(p * BT + bt) * DIM + c]);
    float s = 0.f;
#pragma unroll
    for (int p = 0; p < 8; p++)
        s += g_csum_p[(p * BT + bt) * DIM + c] * __expf(g_cmax_p[(p * BT + bt) * DIM + c] - m);
    g_colmax[bt * DIM + c] = m;
    g_colsum[bt * DIM + c] = s;
}

// ---------------- K5: v_mid[bt,h] = S1^T @ xv ----------------
__global__ __launch_bounds__(256) void k_attmid() {
    const int bt = blockIdx.x, h = blockIdx.y;
    __shared__ float Ls[32][36], XVs[32][36], S1s[32][36];
    const int tid = threadIdx.x, warp = tid >> 5, lane = tid & 31;
    const int ln = tid >> 3, lc = (tid & 7) * 4;
    float acc[4] = {0.f, 0.f, 0.f, 0.f};
    const float4 zero4 = make_float4(0.f, 0.f, 0.f, 0.f);

    for (int ch = 0; ch < 32; ch++) {
        const int ng = ch * 32 + ln;
        const bool valid = ng < NTOK;
        const long row = ((long)bt * NTOK + ng) * DIM + h * 32 + lc;
        float4 lv  = valid ? *(const float4*)(g_L  + row) : zero4;
        float4 xvv = valid ? *(const float4*)(g_xv + row) : zero4;
        *(float4*)&Ls[ln][lc]  = lv;
        *(float4*)&XVs[ln][lc] = xvv;
        __syncthreads();
#pragma unroll
        for (int j = 0; j < 4; j++) {
            const int n = warp * 4 + j;
            const float v = Ls[n][lane];
            float mx = v;
#pragma unroll
            for (int o = 16; o; o >>= 1) mx = fmaxf(mx, __shfl_xor_sync(0xffffffffu, mx, o));
            const float e0 = __expf(v - mx);
            float sm = e0;
#pragma unroll
            for (int o = 16; o; o >>= 1) sm += __shfl_xor_sync(0xffffffffu, sm, o);
            float s1 = e0 / sm;
            if (ch * 32 + n >= NTOK) s1 = 0.f;
            S1s[n][lane] = s1;
        }
        __syncthreads();
#pragma unroll 8
        for (int n = 0; n < 32; n++) {
            const float xvb = XVs[n][lane];
#pragma unroll
            for (int j = 0; j < 4; j++) acc[j] += S1s[n][warp * 4 + j] * xvb;
        }
        __syncthreads();
    }
#pragma unroll
    for (int j = 0; j < 4; j++)
        g_vmid[(((long)bt * HN + h) * RN + warp * 4 + j) * HDIM + lane] = acc[j];
}

// ---------------- K6: S2 softmax + v_out + final combine ----------------
__global__ __launch_bounds__(256) void k_final(
    float* __restrict__ out,
    const float* __restrict__ al, const float* __restrict__ be,
    const float* __restrict__ ma, const float* __restrict__ mb)
{
    __shared__ float vm[HN * RN * HDIM];
    __shared__ float s2s[256];
    const int bt = blockIdx.x / 50, ch = blockIdx.x % 50;
    const int tid = threadIdx.x, h = tid >> 5, d = tid & 31;
    const float sa = sigm(al[0]), sb = sigm(be[0]);
    const float sva = sigm(ma[h]), svb = sigm(mb[h]);

#pragma unroll
    for (int i = 0; i < 32; i++)
        vm[tid + i * 256] = g_vmid[(long)bt * 8192 + tid + i * 256];

    const float cm = g_colmax[bt * DIM + tid];
    const float ci = 1.f / g_colsum[bt * DIM + tid];
    __syncthreads();

    for (int t = 0; t < 20; t++) {
        const long ro = ((long)bt * NTOK + ch * 20 + t) * DIM + tid;
        s2s[tid] = __expf(g_L[ro] - cm) * ci;
        __syncthreads();
        float acc = 0.f;
#pragma unroll
        for (int r = 0; r < 32; r++)
            acc += s2s[h * 32 + r] * vm[(h * 32 + r) * 32 + d];
        out[ro] = sa * g_ffn[ro] + sb * (sva * g_xv[ro] + svb * acc);
        __syncthreads();
    }
}

// ---------------- launch (NO __device__ symbols cross the host boundary) ----------------
extern "C" void kernel_launch(void* const* d_in, const int* in_sizes, int n_in,
                              void* d_out, int out_size) {
    (void)in_sizes; (void)n_in; (void)out_size;
    const float* x     = (const float*)d_in[0];
    const float* z     = (const float*)d_in[1];
    const float* n1w   = (const float*)d_in[2];
    const float* n2w   = (const float*)d_in[3];
    const float* alpha = (const float*)d_in[4];
    const float* beta  = (const float*)d_in[5];
    const float* gamma = (const float*)d_in[6];
    const float* delta = (const float*)d_in[7];
    const float* Wq    = (const float*)d_in[8];
    const float* bq    = (const float*)d_in[9];
    const float* key   = (const float*)d_in[10];
    const float* Wv    = (const float*)d_in[11];
    const float* bv    = (const float*)d_in[12];
    const float* mha_a = (const float*)d_in[13];
    const float* mha_b = (const float*)d_in[14];
    const float* W1    = (const float*)d_in[15];
    const float* b1    = (const float*)d_in[16];
    const float* W2    = (const float*)d_in[17];
    const float* b2    = (const float*)d_in[18];
    const float* W3    = (const float*)d_in[19];
    const float* b3    = (const float*)d_in[20];
    float* out = (float*)d_out;

    // pre-transpose + tf32-round weights into [n][k] (dst resolved device-side by id)
    k_prept<<<dim3(DIM / 32, EDIM / 32), dim3(32, 8)>>>(W1, 0, DIM, EDIM);
    k_prept<<<dim3(DIM / 32, EDIM / 32), dim3(32, 8)>>>(W2, 1, DIM, EDIM);
    k_prept<<<dim3(EDIM / 32, DIM / 32), dim3(32, 8)>>>(W3, 2, EDIM, DIM);
    k_prept<<<dim3(DIM / 32, DIM / 32),  dim3(32, 8)>>>(Wv, 3, DIM, DIM);

    k_weff<<<256, 256>>>(Wq, bq, key);
    k_norm<<<M_TOT / 8, 256>>>(x, z, n1w, n2w, gamma, delta);

    k_dualffn<<<dim3(EDIM / 64, M_TOT / 128), 256>>>(b1, b2);
    k_gemm<<<dim3(DIM / 128, M_TOT / 128), 256>>>(0, b3, EDIM, DIM);      // ffn
    k_gemm<<<dim3(DIM / 128, M_TOT / 128), 256>>>(1, nullptr, DIM, DIM);  // L
    k_gemm<<<dim3(DIM / 128, M_TOT / 128), 256>>>(2, bv, DIM, DIM);       // xv

    k_colstats<<<dim3(BT, 8), 256>>>();
    k_colcomb<<<BT, 256>>>();
    k_attmid<<<dim3(BT, HN), 256>>>();
    k_final<<<BT * 50, 256>>>(out, alpha, beta, mha_a, mha_b);
}

// round 13
// speedup vs baseline: 2.2474x; 1.4033x over previous
#include <cuda_runtime.h>
#include <cuda_fp16.h>
#include <cstdint>

// ---------------- problem constants ----------------
#define BT     96
#define NTOK   1000
#define M_TOT  96000
#define DIM    256
#define EDIM   1024
#define HN     8
#define HDIM   32
#define RN     32

// ---------------- scratch (device bss) ----------------
__device__ __half g_x1h[M_TOT * DIM];
__device__ __half g_z1h[M_TOT * DIM];
__device__ __half g_Gh [M_TOT * EDIM];
__device__ float  g_ffn[M_TOT * DIM];
__device__ float  g_L  [M_TOT * DIM];
__device__ float  g_xv [M_TOT * DIM];
__device__ __half g_weffh[DIM * DIM];      // [n][k]
__device__ float  g_abias[DIM];
__device__ float  g_colmax[BT * DIM];
__device__ float  g_colsum[BT * DIM];
__device__ float  g_cmax_p[8 * BT * DIM];
__device__ float  g_csum_p[8 * BT * DIM];
__device__ float  g_vmid[BT * HN * RN * HDIM];
// pre-transposed half weights [n][k]
__device__ __half g_W1h[EDIM * DIM];
__device__ __half g_W2h[EDIM * DIM];
__device__ __half g_W3h[DIM * EDIM];
__device__ __half g_Wvh[DIM * DIM];

// ---------------- helpers ----------------
__device__ __forceinline__ float sigm(float v) { return 1.f / (1.f + __expf(-v)); }
__device__ __forceinline__ uint32_t smem_u32(const void* p) {
    uint32_t a;
    asm("{ .reg .u64 t; cvta.to.shared.u64 t, %1; cvt.u32.u64 %0, t; }" : "=r"(a) : "l"(p));
    return a;
}
__device__ __forceinline__ void mma16(float* c, const unsigned* a, const unsigned* b) {
    asm volatile(
        "mma.sync.aligned.m16n8k16.row.col.f32.f16.f16.f32 "
        "{%0,%1,%2,%3},{%4,%5,%6,%7},{%8,%9},{%0,%1,%2,%3};"
        : "+f"(c[0]), "+f"(c[1]), "+f"(c[2]), "+f"(c[3])
        : "r"(a[0]), "r"(a[1]), "r"(a[2]), "r"(a[3]), "r"(b[0]), "r"(b[1]));
}
__device__ __forceinline__ void ldm4(uint32_t addr, unsigned* r) {
    asm volatile("ldmatrix.sync.aligned.m8n8.x4.shared.b16 {%0,%1,%2,%3}, [%4];"
        : "=r"(r[0]), "=r"(r[1]), "=r"(r[2]), "=r"(r[3]) : "r"(addr));
}

// smem pitch: 32 data halves + 8 pad = 40 halves = 80 bytes per row
#define AP 40

// ---------------- K_prept: dst[n*K+k] = half(src[k*N+n]); dst resolved DEVICE-SIDE ----------------
__global__ void k_prept(const float* __restrict__ src, int which, int K, int N) {
    __half* __restrict__ dst = (which == 0) ? g_W1h : (which == 1) ? g_W2h
                             : (which == 2) ? g_W3h : g_Wvh;
    __shared__ float t[32][33];
    const int k0 = blockIdx.x * 32, n0 = blockIdx.y * 32;
    for (int i = threadIdx.y; i < 32; i += 8)
        t[i][threadIdx.x] = src[(long)(k0 + i) * N + n0 + threadIdx.x];
    __syncthreads();
    for (int i = threadIdx.y; i < 32; i += 8)
        dst[(long)(n0 + i) * K + k0 + threadIdx.x] = __float2half(t[threadIdx.x][i]);
}

// ---------------- K0: weffh[n][k] + abias ----------------
__global__ void k_weff(const float* __restrict__ Wq, const float* __restrict__ bq,
                       const float* __restrict__ key) {
    const int i = blockIdx.x;       // k
    const int c = threadIdx.x;      // n = h*32 + r
    const int h = c >> 5, r = c & 31;
    const float sc = 0.17677669529663687f;
    float s = 0.f;
#pragma unroll
    for (int d = 0; d < 32; d++)
        s += Wq[i * DIM + h * 32 + d] * key[(r * HN + h) * HDIM + d];
    g_weffh[c * DIM + i] = __float2half(s * sc);
    if (i == 0) {
        float b = 0.f;
#pragma unroll
        for (int d = 0; d < 32; d++)
            b += bq[h * 32 + d] * key[(r * HN + h) * HDIM + d];
        g_abias[c] = b * sc;
    }
}

// ---------------- K1: fused RMSNorms, half outputs ----------------
__global__ __launch_bounds__(256) void k_norm(
    const float* __restrict__ x, const float* __restrict__ z,
    const float* __restrict__ w1, const float* __restrict__ w2,
    const float* __restrict__ ga, const float* __restrict__ de)
{
    const int warp = threadIdx.x >> 5, lane = threadIdx.x & 31;
    const long tok = (long)blockIdx.x * 8 + warp;
    const float sg = sigm(ga[0]), sd = sigm(de[0]);

    const float4* xr = (const float4*)x + tok * 64;
    const float4* zr = (const float4*)z + tok * 64;
    float4 xa = xr[lane], xb = xr[lane + 32];

    float ss = xa.x*xa.x + xa.y*xa.y + xa.z*xa.z + xa.w*xa.w
             + xb.x*xb.x + xb.y*xb.y + xb.z*xb.z + xb.w*xb.w;
#pragma unroll
    for (int o = 16; o; o >>= 1) ss += __shfl_xor_sync(0xffffffffu, ss, o);
    const float r1 = rsqrtf(ss * (1.f / 256.f) + 1e-6f);

    float4 wa = ((const float4*)w1)[lane], wb = ((const float4*)w1)[lane + 32];
    float4 x1a, x1b;
    x1a.x = xa.x*r1*wa.x; x1a.y = xa.y*r1*wa.y; x1a.z = xa.z*r1*wa.z; x1a.w = xa.w*r1*wa.w;
    x1b.x = xb.x*r1*wb.x; x1b.y = xb.y*r1*wb.y; x1b.z = xb.z*r1*wb.z; x1b.w = xb.w*r1*wb.w;
    __half2* x1o = (__half2*)g_x1h + tok * 128;
    x1o[2*lane]      = __floats2half2_rn(x1a.x, x1a.y);
    x1o[2*lane + 1]  = __floats2half2_rn(x1a.z, x1a.w);
    x1o[64 + 2*lane]     = __floats2half2_rn(x1b.x, x1b.y);
    x1o[64 + 2*lane + 1] = __floats2half2_rn(x1b.z, x1b.w);

    float4 za = zr[lane], zb = zr[lane + 32];
    float4 ya, yb;
    ya.x = sg*x1a.x + sd*za.x; ya.y = sg*x1a.y + sd*za.y;
    ya.z = sg*x1a.z + sd*za.z; ya.w = sg*x1a.w + sd*za.w;
    yb.x = sg*x1b.x + sd*zb.x; yb.y = sg*x1b.y + sd*zb.y;
    yb.z = sg*x1b.z + sd*zb.z; yb.w = sg*x1b.w + sd*zb.w;

    float s2 = ya.x*ya.x + ya.y*ya.y + ya.z*ya.z + ya.w*ya.w
             + yb.x*yb.x + yb.y*yb.y + yb.z*yb.z + yb.w*yb.w;
#pragma unroll
    for (int o = 16; o; o >>= 1) s2 += __shfl_xor_sync(0xffffffffu, s2, o);
    const float r2 = rsqrtf(s2 * (1.f / 256.f) + 1e-6f);

    float4 va = ((const float4*)w2)[lane], vb = ((const float4*)w2)[lane + 32];
    __half2* z1o = (__half2*)g_z1h + tok * 128;
    z1o[2*lane]     = __floats2half2_rn(ya.x*r2*va.x, ya.y*r2*va.y);
    z1o[2*lane + 1] = __floats2half2_rn(ya.z*r2*va.z, ya.w*r2*va.w);
    z1o[64 + 2*lane]     = __floats2half2_rn(yb.x*r2*vb.x, yb.y*r2*vb.y);
    z1o[64 + 2*lane + 1] = __floats2half2_rn(yb.z*r2*vb.z, yb.w*r2*vb.w);
}

// ---------------- K2: dual SwiGLU GEMM, fp16 m16n8k16 ----------------
// block tile 128(M) x 64(N per matrix), 8 warps (2x4), warp tile 64x16 per matrix; K-step 32.
__global__ __launch_bounds__(256, 2) void k_dualffn(
    const float* __restrict__ b1, const float* __restrict__ b2)
{
    __shared__ __align__(16) __half As[128][AP];
    __shared__ __align__(16) __half B1s[64][AP];
    __shared__ __align__(16) __half B2s[64][AP];
    const int K = DIM;
    const int tid = threadIdx.x;
    const int warp = tid >> 5, lane = tid & 31, grp = lane >> 2, tg = lane & 3;
    const int wm0 = (warp >> 2) * 64, wn0 = (warp & 3) * 16;
    const int m0 = blockIdx.y * 128, n0 = blockIdx.x * 64;

    float acc1[4][2][4], acc2[4][2][4];
#pragma unroll
    for (int a = 0; a < 4; a++)
#pragma unroll
        for (int b = 0; b < 2; b++)
#pragma unroll
            for (int c = 0; c < 4; c++) { acc1[a][b][c] = 0.f; acc2[a][b][c] = 0.f; }

    // staging: A 128x32 halves (2 uint4/thread), B1/B2 64x32 halves (1 uint4/thread each)
    int arow[2];
#pragma unroll
    for (int i = 0; i < 2; i++) arow[i] = (tid + i * 256) >> 2;
    const int brow = tid >> 2;
    const int acol8 = (tid & 3) * 8;       // halves

    // ldmatrix lane geometry (b16): row = (l&7)+((l>>3)&1)*8, byte-col = (l>>4)*16
    const int lrow = (lane & 7) + ((lane >> 3) & 1) * 8;
    const int lcolB = (lane >> 4) * 16;
    const uint32_t aAd  = smem_u32(&As[0][0])  + (uint32_t)((wm0 + lrow) * 80 + lcolB);
    const uint32_t b1Ad = smem_u32(&B1s[0][0]) + (uint32_t)((wn0 + lrow) * 80 + lcolB);
    const uint32_t b2Ad = smem_u32(&B2s[0][0]) + (uint32_t)((wn0 + lrow) * 80 + lcolB);

    uint4 ar[2], b1r, b2r;
    const int KT = K >> 5;   // 8

#define LOADG_D(kt) do { int kb = (kt) * 32;                                               \
    _Pragma("unroll") for (int i = 0; i < 2; i++)                                          \
        ar[i] = *(const uint4*)(g_x1h + (long)(m0 + arow[i]) * K + kb + acol8);            \
    b1r = *(const uint4*)(g_W1h + (long)(n0 + brow) * K + kb + acol8);                     \
    b2r = *(const uint4*)(g_W2h + (long)(n0 + brow) * K + kb + acol8); } while (0)

#define STOS_D() do {                                                                      \
    _Pragma("unroll") for (int i = 0; i < 2; i++)                                          \
        *(uint4*)&As[arow[i]][acol8] = ar[i];                                              \
    *(uint4*)&B1s[brow][acol8] = b1r;                                                      \
    *(uint4*)&B2s[brow][acol8] = b2r; } while (0)

    LOADG_D(0); STOS_D();
    for (int kt = 0; kt < KT; kt++) {
        __syncthreads();
        if (kt + 1 < KT) LOADG_D(kt + 1);
#pragma unroll
        for (int kk = 0; kk < 2; kk++) {
            const uint32_t ko = kk * 32;   // 16 halves = 32B
            unsigned a[4][4], bb1[2][2], bb2[2][2], t[4];
#pragma unroll
            for (int mf = 0; mf < 4; mf++) ldm4(aAd + mf * 1280 + ko, a[mf]);
            ldm4(b1Ad + ko, t);
            bb1[0][0] = t[0]; bb1[0][1] = t[2]; bb1[1][0] = t[1]; bb1[1][1] = t[3];
            ldm4(b2Ad + ko, t);
            bb2[0][0] = t[0]; bb2[0][1] = t[2]; bb2[1][0] = t[1]; bb2[1][1] = t[3];
#pragma unroll
            for (int mf = 0; mf < 4; mf++)
#pragma unroll
                for (int nf = 0; nf < 2; nf++) {
                    mma16(acc1[mf][nf], a[mf], bb1[nf]);
                    mma16(acc2[mf][nf], a[mf], bb2[nf]);
                }
        }
        __syncthreads();
        if (kt + 1 < KT) STOS_D();
    }
#undef LOADG_D
#undef STOS_D

#pragma unroll
    for (int mf = 0; mf < 4; mf++) {
        const int gm = m0 + wm0 + mf * 16 + grp;
#pragma unroll
        for (int nf = 0; nf < 2; nf++) {
            const int gn = n0 + wn0 + nf * 8 + tg * 2;
            const float c1x = b1[gn], c1y = b1[gn + 1];
            const float c2x = b2[gn], c2y = b2[gn + 1];
            float h1, h2, v0, v1;
            h1 = acc1[mf][nf][0] + c1x; h2 = acc2[mf][nf][0] + c2x; v0 = h1 * sigm(h1) * h2;
            h1 = acc1[mf][nf][1] + c1y; h2 = acc2[mf][nf][1] + c2y; v1 = h1 * sigm(h1) * h2;
            *(__half2*)(g_Gh + (long)gm * EDIM + gn) = __floats2half2_rn(v0, v1);
            h1 = acc1[mf][nf][2] + c1x; h2 = acc2[mf][nf][2] + c2x; v0 = h1 * sigm(h1) * h2;
            h1 = acc1[mf][nf][3] + c1y; h2 = acc2[mf][nf][3] + c2y; v1 = h1 * sigm(h1) * h2;
            *(__half2*)(g_Gh + (long)(gm + 8) * EDIM + gn) = __floats2half2_rn(v0, v1);
        }
    }
}

// ---------------- K3: generic GEMM C = A@W^T + bias, fp16 m16n8k16 ----------------
// mode 0: A=g_Gh,  Wt=g_W3h,   C=g_ffn, bias=b3      (K=1024)
// mode 1: A=g_z1h, Wt=g_weffh, C=g_L,   bias=g_abias (K=256)
// mode 2: A=g_x1h, Wt=g_Wvh,   C=g_xv,  bias=bv      (K=256)
__global__ __launch_bounds__(256, 2) void k_gemm(
    int mode, const float* __restrict__ biasExt, int K, int N)
{
    const __half* __restrict__ A  = (mode == 0) ? g_Gh : (mode == 1) ? g_z1h : g_x1h;
    const __half* __restrict__ Wt = (mode == 0) ? g_W3h : (mode == 1) ? g_weffh : g_Wvh;
    float* __restrict__ C = (mode == 0) ? g_ffn : (mode == 1) ? g_L : g_xv;
    const float* __restrict__ bias = (mode == 1) ? g_abias : biasExt;

    __shared__ __align__(16) __half As[128][AP];
    __shared__ __align__(16) __half Bs[128][AP];
    const int tid = threadIdx.x;
    const int warp = tid >> 5, lane = tid & 31, grp = lane >> 2, tg = lane & 3;
    const int wm0 = (warp >> 2) * 64, wn0 = (warp & 3) * 32;
    const int m0 = blockIdx.y * 128, n0 = blockIdx.x * 128;

    float acc[4][4][4];
#pragma unroll
    for (int a = 0; a < 4; a++)
#pragma unroll
        for (int b = 0; b < 4; b++)
#pragma unroll
            for (int c = 0; c < 4; c++) acc[a][b][c] = 0.f;

    int arow[2];
#pragma unroll
    for (int i = 0; i < 2; i++) arow[i] = (tid + i * 256) >> 2;
    const int acol8 = (tid & 3) * 8;

    const int lrow = (lane & 7) + ((lane >> 3) & 1) * 8;
    const int lcolB = (lane >> 4) * 16;
    const uint32_t aAd = smem_u32(&As[0][0]) + (uint32_t)((wm0 + lrow) * 80 + lcolB);
    const uint32_t bAd = smem_u32(&Bs[0][0]) + (uint32_t)((wn0 + lrow) * 80 + lcolB);

    uint4 ar[2], br[2];
    const int KT = K >> 5;

#define LOADG_G(kt) do { int kb = (kt) * 32;                                               \
    _Pragma("unroll") for (int i = 0; i < 2; i++) {                                        \
        ar[i] = *(const uint4*)(A  + (long)(m0 + arow[i]) * K + kb + acol8);               \
        br[i] = *(const uint4*)(Wt + (long)(n0 + arow[i]) * K + kb + acol8); } } while (0)

#define STOS_G() do {                                                                      \
    _Pragma("unroll") for (int i = 0; i < 2; i++) {                                        \
        *(uint4*)&As[arow[i]][acol8] = ar[i];                                              \
        *(uint4*)&Bs[arow[i]][acol8] = br[i]; } } while (0)

    LOADG_G(0); STOS_G();
    for (int kt = 0; kt < KT; kt++) {
        __syncthreads();
        if (kt + 1 < KT) LOADG_G(kt + 1);
#pragma unroll
        for (int kk = 0; kk < 2; kk++) {
            const uint32_t ko = kk * 32;
            unsigned a[4][4], b[4][2], t[4];
#pragma unroll
            for (int mf = 0; mf < 4; mf++) ldm4(aAd + mf * 1280 + ko, a[mf]);
            ldm4(bAd + ko, t);
            b[0][0] = t[0]; b[0][1] = t[2]; b[1][0] = t[1]; b[1][1] = t[3];
            ldm4(bAd + 1280 + ko, t);
            b[2][0] = t[0]; b[2][1] = t[2]; b[3][0] = t[1]; b[3][1] = t[3];
#pragma unroll
            for (int mf = 0; mf < 4; mf++)
#pragma unroll
                for (int nf = 0; nf < 4; nf++)
                    mma16(acc[mf][nf], a[mf], b[nf]);
        }
        __syncthreads();
        if (kt + 1 < KT) STOS_G();
    }
#undef LOADG_G
#undef STOS_G

#pragma unroll
    for (int mf = 0; mf < 4; mf++) {
        const int gm = m0 + wm0 + mf * 16 + grp;
#pragma unroll
        for (int nf = 0; nf < 4; nf++) {
            const int gn = n0 + wn0 + nf * 8 + tg * 2;
            const float2 bb = *(const float2*)(bias + gn);
            float2 o0 = { acc[mf][nf][0] + bb.x, acc[mf][nf][1] + bb.y };
            float2 o1 = { acc[mf][nf][2] + bb.x, acc[mf][nf][3] + bb.y };
            *(float2*)(C + (long)gm * N + gn) = o0;
            *(float2*)(C + (long)(gm + 8) * N + gn) = o1;
        }
    }
}

// ---------------- K4a: partial per-(bt,col) max/sum over 125-row slabs ----------------
__global__ __launch_bounds__(256) void k_colstats() {
    const int bt = blockIdx.x, part = blockIdx.y, c = threadIdx.x;
    const float* base = g_L + ((long)bt * NTOK + part * 125) * DIM + c;
    float m = -3.0e38f, s = 0.f;
    for (int c5 = 0; c5 < 25; c5++) {
        float v[5];
#pragma unroll
        for (int j = 0; j < 5; j++) v[j] = base[(long)(c5 * 5 + j) * DIM];
        float lm = v[0];
#pragma unroll
        for (int j = 1; j < 5; j++) lm = fmaxf(lm, v[j]);
        const float nm = fmaxf(m, lm);
        s *= __expf(m - nm);
#pragma unroll
        for (int j = 0; j < 5; j++) s += __expf(v[j] - nm);
        m = nm;
    }
    g_cmax_p[(part * BT + bt) * DIM + c] = m;
    g_csum_p[(part * BT + bt) * DIM + c] = s;
}

// ---------------- K4b: combine partials ----------------
__global__ __launch_bounds__(256) void k_colcomb() {
    const int bt = blockIdx.x, c = threadIdx.x;
    float m = -3.0e38f;
#pragma unroll
    for (int p = 0; p < 8; p++) m = fmaxf(m, g_cmax_p[(p * BT + bt) * DIM + c]);
    float s = 0.f;
#pragma unroll
    for (int p = 0; p < 8; p++)
        s += g_csum_p[(p * BT + bt) * DIM + c] * __expf(g_cmax_p[(p * BT + bt) * DIM + c] - m);
    g_colmax[bt * DIM + c] = m;
    g_colsum[bt * DIM + c] = s;
}

// ---------------- K5: v_mid[bt,h] = S1^T @ xv ----------------
__global__ __launch_bounds__(256) void k_attmid() {
    const int bt = blockIdx.x, h = blockIdx.y;
    __shared__ float Ls[32][36], XVs[32][36], S1s[32][36];
    const int tid = threadIdx.x, warp = tid >> 5, lane = tid & 31;
    const int ln = tid >> 3, lc = (tid & 7) * 4;
    float acc[4] = {0.f, 0.f, 0.f, 0.f};
    const float4 zero4 = make_float4(0.f, 0.f, 0.f, 0.f);

    for (int ch = 0; ch < 32; ch++) {
        const int ng = ch * 32 + ln;
        const bool valid = ng < NTOK;
        const long row = ((long)bt * NTOK + ng) * DIM + h * 32 + lc;
        float4 lv  = valid ? *(const float4*)(g_L  + row) : zero4;
        float4 xvv = valid ? *(const float4*)(g_xv + row) : zero4;
        *(float4*)&Ls[ln][lc]  = lv;
        *(float4*)&XVs[ln][lc] = xvv;
        __syncthreads();
#pragma unroll
        for (int j = 0; j < 4; j++) {
            const int n = warp * 4 + j;
            const float v = Ls[n][lane];
            float mx = v;
#pragma unroll
            for (int o = 16; o; o >>= 1) mx = fmaxf(mx, __shfl_xor_sync(0xffffffffu, mx, o));
            const float e0 = __expf(v - mx);
            float sm = e0;
#pragma unroll
            for (int o = 16; o; o >>= 1) sm += __shfl_xor_sync(0xffffffffu, sm, o);
            float s1 = e0 / sm;
            if (ch * 32 + n >= NTOK) s1 = 0.f;
            S1s[n][lane] = s1;
        }
        __syncthreads();
#pragma unroll 8
        for (int n = 0; n < 32; n++) {
            const float xvb = XVs[n][lane];
#pragma unroll
            for (int j = 0; j < 4; j++) acc[j] += S1s[n][warp * 4 + j] * xvb;
        }
        __syncthreads();
    }
#pragma unroll
    for (int j = 0; j < 4; j++)
        g_vmid[(((long)bt * HN + h) * RN + warp * 4 + j) * HDIM + lane] = acc[j];
}

// ---------------- K6: S2 softmax + v_out + final combine ----------------
__global__ __launch_bounds__(256) void k_final(
    float* __restrict__ out,
    const float* __restrict__ al, const float* __restrict__ be,
    const float* __restrict__ ma, const float* __restrict__ mb)
{
    __shared__ float vm[HN * RN * HDIM];
    __shared__ float s2s[256];
    const int bt = blockIdx.x / 50, ch = blockIdx.x % 50;
    const int tid = threadIdx.x, h = tid >> 5, d = tid & 31;
    const float sa = sigm(al[0]), sb = sigm(be[0]);
    const float sva = sigm(ma[h]), svb = sigm(mb[h]);

#pragma unroll
    for (int i = 0; i < 32; i++)
        vm[tid + i * 256] = g_vmid[(long)bt * 8192 + tid + i * 256];

    const float cm = g_colmax[bt * DIM + tid];
    const float ci = 1.f / g_colsum[bt * DIM + tid];
    __syncthreads();

    for (int t = 0; t < 20; t++) {
        const long ro = ((long)bt * NTOK + ch * 20 + t) * DIM + tid;
        s2s[tid] = __expf(g_L[ro] - cm) * ci;
        __syncthreads();
        float acc = 0.f;
#pragma unroll
        for (int r = 0; r < 32; r++)
            acc += s2s[h * 32 + r] * vm[(h * 32 + r) * 32 + d];
        out[ro] = sa * g_ffn[ro] + sb * (sva * g_xv[ro] + svb * acc);
        __syncthreads();
    }
}

// ---------------- launch (NO __device__ symbols cross the host boundary) ----------------
extern "C" void kernel_launch(void* const* d_in, const int* in_sizes, int n_in,
                              void* d_out, int out_size) {
    (void)in_sizes; (void)n_in; (void)out_size;
    const float* x     = (const float*)d_in[0];
    const float* z     = (const float*)d_in[1];
    const float* n1w   = (const float*)d_in[2];
    const float* n2w   = (const float*)d_in[3];
    const float* alpha = (const float*)d_in[4];
    const float* beta  = (const float*)d_in[5];
    const float* gamma = (const float*)d_in[6];
    const float* delta = (const float*)d_in[7];
    const float* Wq    = (const float*)d_in[8];
    const float* bq    = (const float*)d_in[9];
    const float* key   = (const float*)d_in[10];
    const float* Wv    = (const float*)d_in[11];
    const float* bv    = (const float*)d_in[12];
    const float* mha_a = (const float*)d_in[13];
    const float* mha_b = (const float*)d_in[14];
    const float* W1    = (const float*)d_in[15];
    const float* b1    = (const float*)d_in[16];
    const float* W2    = (const float*)d_in[17];
    const float* b2    = (const float*)d_in[18];
    const float* W3    = (const float*)d_in[19];
    const float* b3    = (const float*)d_in[20];
    float* out = (float*)d_out;

    // pre-transpose + fp16-round weights into [n][k] (dst resolved device-side by id)
    k_prept<<<dim3(DIM / 32, EDIM / 32), dim3(32, 8)>>>(W1, 0, DIM, EDIM);
    k_prept<<<dim3(DIM / 32, EDIM / 32), dim3(32, 8)>>>(W2, 1, DIM, EDIM);
    k_prept<<<dim3(EDIM / 32, DIM / 32), dim3(32, 8)>>>(W3, 2, EDIM, DIM);
    k_prept<<<dim3(DIM / 32, DIM / 32),  dim3(32, 8)>>>(Wv, 3, DIM, DIM);

    k_weff<<<256, 256>>>(Wq, bq, key);
    k_norm<<<M_TOT / 8, 256>>>(x, z, n1w, n2w, gamma, delta);

    k_dualffn<<<dim3(EDIM / 64, M_TOT / 128), 256>>>(b1, b2);
    k_gemm<<<dim3(DIM / 128, M_TOT / 128), 256>>>(0, b3, EDIM, DIM);      // ffn
    k_gemm<<<dim3(DIM / 128, M_TOT / 128), 256>>>(1, nullptr, DIM, DIM);  // L
    k_gemm<<<dim3(DIM / 128, M_TOT / 128), 256>>>(2, bv, DIM, DIM);       // xv

    k_colstats<<<dim3(BT, 8), 256>>>();
    k_colcomb<<<BT, 256>>>();
    k_attmid<<<dim3(BT, HN), 256>>>();
    k_final<<<BT * 50, 256>>>(out, alpha, beta, mha_a, mha_b);
}